// round 1
// baseline (speedup 1.0000x reference)
#include <cuda_runtime.h>
#include <cuda_bf16.h>
#include <math.h>

// ---------------------------------------------------------------------------
// TidalTransformer: B=4, S=1024, H=1024, NH=16, DK=64, DF=4096, L=4, V=32000
// All fp32. Round-1 baseline: tiled SGEMM + flash attention + fused LN.
// ---------------------------------------------------------------------------

#define Bz   4
#define Sz   1024
#define Hz   1024
#define NHz  16
#define DKz  64
#define DFz  4096
#define Lz   4
#define Vz   32000
#define Mz   (Bz * Sz)   // 4096 rows

// ------------------------- scratch (device globals) ------------------------
__device__ float g_x[(size_t)Mz * Hz];
__device__ float g_q[(size_t)Mz * Hz];
__device__ float g_k[(size_t)Mz * Hz];
__device__ float g_v[(size_t)Mz * Hz];
__device__ float g_attn[(size_t)Mz * Hz];
__device__ float g_tmp[(size_t)Mz * Hz];
__device__ float g_ff[(size_t)Mz * DFz];

// ------------------------------- embedding ---------------------------------
__global__ void embed_kernel(const int* __restrict__ ids,
                             const float* __restrict__ emb,
                             float* __restrict__ x)
{
    int row = blockIdx.x;                 // 0..4095
    int tid = threadIdx.x;                // 256 threads, 4 floats each
    int id  = ids[row];
    float4 v = *(const float4*)(emb + (size_t)id * Hz + tid * 4);
    v.x *= 32.0f; v.y *= 32.0f; v.z *= 32.0f; v.w *= 32.0f;
    *(float4*)(x + (size_t)row * Hz + tid * 4) = v;
}

// ------------------------------ tiled SGEMM --------------------------------
// C[M,N] = A[M,K] @ W[K,N] + bias ; op: 0=none, 1=exact GELU, 2=row mask
#define BM 128
#define BN 128
#define BKt 8
#define TM 8
#define TN 8

__global__ __launch_bounds__(256, 2)
void gemm_kernel(const float* __restrict__ A, const float* __restrict__ W,
                 const float* __restrict__ bias, float* __restrict__ C,
                 int M, int N, int K, int op, const int* __restrict__ start_pos)
{
    __shared__ float As[BKt][BM];
    __shared__ float Bs[BKt][BN];

    int tid = threadIdx.x;
    int tx = tid & 15;         // 0..15 -> col group
    int ty = tid >> 4;         // 0..15 -> row group
    int m0 = blockIdx.y * BM;
    int n0 = blockIdx.x * BN;

    int arow = tid >> 1;            // 0..127
    int acol = (tid & 1) * 4;       // 0 or 4
    int brow = tid >> 5;            // 0..7
    int bcol = (tid & 31) * 4;      // 0..124

    float acc[TM][TN];
    #pragma unroll
    for (int i = 0; i < TM; i++)
        #pragma unroll
        for (int j = 0; j < TN; j++) acc[i][j] = 0.f;

    for (int k0 = 0; k0 < K; k0 += BKt) {
        float4 av = *(const float4*)(A + (size_t)(m0 + arow) * K + k0 + acol);
        float4 bv = *(const float4*)(W + (size_t)(k0 + brow) * N + n0 + bcol);
        As[acol + 0][arow] = av.x;
        As[acol + 1][arow] = av.y;
        As[acol + 2][arow] = av.z;
        As[acol + 3][arow] = av.w;
        *(float4*)&Bs[brow][bcol] = bv;
        __syncthreads();

        #pragma unroll
        for (int kk = 0; kk < BKt; ++kk) {
            float af[TM], bfv[TN];
            #pragma unroll
            for (int i = 0; i < TM; i++) af[i] = As[kk][ty * TM + i];
            #pragma unroll
            for (int j = 0; j < TN; j++) bfv[j] = Bs[kk][tx * TN + j];
            #pragma unroll
            for (int i = 0; i < TM; i++)
                #pragma unroll
                for (int j = 0; j < TN; j++)
                    acc[i][j] = fmaf(af[i], bfv[j], acc[i][j]);
        }
        __syncthreads();
    }

    #pragma unroll
    for (int i = 0; i < TM; i++) {
        int row = m0 + ty * TM + i;
        bool zero = false;
        if (op == 2) {
            int bidx = row >> 10;
            int s    = row & 1023;
            zero = (s < start_pos[bidx]);
        }
        #pragma unroll
        for (int j = 0; j < TN; j++) {
            int col = n0 + tx * TN + j;
            float v = acc[i][j] + bias[col];
            if (op == 1) v = 0.5f * v * (1.0f + erff(v * 0.70710678118654752f));
            if (zero) v = 0.f;
            C[(size_t)row * N + col] = v;
        }
    }
}

// --------------------------- flash attention -------------------------------
// grid (S/64, B*NH), 256 threads. Thread (r = tid>>2, c = tid&3).
// Online softmax with alibi + tidal mask. Q pre-scaled by 1/8.
#define ALD 65
#define ATTN_SMEM (3 * 64 * ALD * 4)

__global__ __launch_bounds__(256)
void attn_kernel(const float* __restrict__ Q, const float* __restrict__ Kt,
                 const float* __restrict__ V, float* __restrict__ O,
                 const int* __restrict__ start_pos)
{
    extern __shared__ float sm[];
    float* sq = sm;
    float* sk = sm + 64 * ALD;
    float* sv = sm + 2 * 64 * ALD;

    int tid = threadIdx.x;
    int r = tid >> 2;        // query row within tile (0..63)
    int c = tid & 3;         // column slice (0..3)
    int qt = blockIdx.x;     // 0..15
    int bh = blockIdx.y;     // 0..63
    int b = bh >> 4, h = bh & 15;
    int sp = start_pos[b];
    float slope = exp2f(-0.5f * (float)(h + 1));

    size_t base = (size_t)b * Sz * Hz + (size_t)h * DKz;

    // load Q tile, pre-scale by 1/sqrt(DK)=1/8
    for (int i = tid; i < 64 * 16; i += 256) {
        int row = i >> 4, d4 = (i & 15) * 4;
        float4 v = *(const float4*)(Q + base + (size_t)(qt * 64 + row) * Hz + d4);
        sq[row * ALD + d4 + 0] = v.x * 0.125f;
        sq[row * ALD + d4 + 1] = v.y * 0.125f;
        sq[row * ALD + d4 + 2] = v.z * 0.125f;
        sq[row * ALD + d4 + 3] = v.w * 0.125f;
    }

    float m_r = -1e30f, l_r = 0.f;
    float oacc[64];
    #pragma unroll
    for (int d = 0; d < 64; d++) oacc[d] = 0.f;

    int ig = qt * 64 + r;
    int ktmax = (qt * 64 >= sp) ? qt : 15;

    for (int kt = 0; kt <= ktmax; ++kt) {
        __syncthreads();
        for (int i = tid; i < 64 * 16; i += 256) {
            int row = i >> 4, d4 = (i & 15) * 4;
            float4 kv = *(const float4*)(Kt + base + (size_t)(kt * 64 + row) * Hz + d4);
            sk[row * ALD + d4 + 0] = kv.x; sk[row * ALD + d4 + 1] = kv.y;
            sk[row * ALD + d4 + 2] = kv.z; sk[row * ALD + d4 + 3] = kv.w;
            float4 vv = *(const float4*)(V + base + (size_t)(kt * 64 + row) * Hz + d4);
            sv[row * ALD + d4 + 0] = vv.x; sv[row * ALD + d4 + 1] = vv.y;
            sv[row * ALD + d4 + 2] = vv.z; sv[row * ALD + d4 + 3] = vv.w;
        }
        __syncthreads();

        float sc[16];
        #pragma unroll
        for (int jj = 0; jj < 16; jj++) {
            int j = jj * 4 + c;
            float dot = 0.f;
            #pragma unroll
            for (int d = 0; d < 64; d++)
                dot = fmaf(sq[r * ALD + d], sk[j * ALD + d], dot);
            int jg = kt * 64 + j;
            bool ok = (jg <= ig) || (ig < sp) || (jg < sp);
            sc[jj] = ok ? dot + slope * (float)(jg - sp) : -1e9f;
        }

        float tmax = sc[0];
        #pragma unroll
        for (int jj = 1; jj < 16; jj++) tmax = fmaxf(tmax, sc[jj]);
        tmax = fmaxf(tmax, __shfl_xor_sync(0xffffffffu, tmax, 1));
        tmax = fmaxf(tmax, __shfl_xor_sync(0xffffffffu, tmax, 2));

        float m_new = fmaxf(m_r, tmax);
        float scl = expf(m_r - m_new);
        float lsum = 0.f;
        #pragma unroll
        for (int jj = 0; jj < 16; jj++) {
            float p = expf(sc[jj] - m_new);
            sc[jj] = p;
            lsum += p;
        }
        lsum += __shfl_xor_sync(0xffffffffu, lsum, 1);
        lsum += __shfl_xor_sync(0xffffffffu, lsum, 2);
        l_r = l_r * scl + lsum;
        m_r = m_new;

        #pragma unroll
        for (int d = 0; d < 64; d++) oacc[d] *= scl;
        #pragma unroll
        for (int jj = 0; jj < 16; jj++) {
            int kk = jj * 4 + c;
            float p = sc[jj];
            #pragma unroll
            for (int d = 0; d < 64; d++)
                oacc[d] = fmaf(p, sv[kk * ALD + d], oacc[d]);
        }
    }

    // reduce partial outputs across the 4 lanes of this row group
    #pragma unroll
    for (int d = 0; d < 64; d++) {
        oacc[d] += __shfl_xor_sync(0xffffffffu, oacc[d], 1);
        oacc[d] += __shfl_xor_sync(0xffffffffu, oacc[d], 2);
    }
    float inv = 1.f / l_r;
    size_t orow = base + (size_t)(qt * 64 + r) * Hz;
    #pragma unroll
    for (int jj = 0; jj < 16; jj++) {
        int d = c * 16 + jj;
        O[orow + d] = oacc[d] * inv;
    }
}

// ------------------------ fused residual + layernorm -----------------------
__inline__ __device__ float warp_sum(float v) {
    #pragma unroll
    for (int o = 16; o; o >>= 1) v += __shfl_xor_sync(0xffffffffu, v, o);
    return v;
}

__global__ void add_ln_kernel(float* __restrict__ x, const float* __restrict__ t,
                              const float* __restrict__ g, const float* __restrict__ b)
{
    int row = blockIdx.x;
    int tid = threadIdx.x;     // 256, 4 floats each
    size_t off = (size_t)row * Hz + tid * 4;

    float4 xv = *(const float4*)(x + off);
    float4 tv = *(const float4*)(t + off);
    float v0 = xv.x + tv.x, v1 = xv.y + tv.y, v2 = xv.z + tv.z, v3 = xv.w + tv.w;

    float s  = v0 + v1 + v2 + v3;
    float s2 = v0 * v0 + v1 * v1 + v2 * v2 + v3 * v3;

    __shared__ float sh1[8], sh2[8];
    int lane = tid & 31, wid = tid >> 5;
    s  = warp_sum(s);
    s2 = warp_sum(s2);
    if (lane == 0) { sh1[wid] = s; sh2[wid] = s2; }
    __syncthreads();
    if (wid == 0) {
        float a = (lane < 8) ? sh1[lane] : 0.f;
        float c = (lane < 8) ? sh2[lane] : 0.f;
        a = warp_sum(a);
        c = warp_sum(c);
        if (lane == 0) { sh1[0] = a; sh2[0] = c; }
    }
    __syncthreads();

    float mu  = sh1[0] * (1.0f / Hz);
    float var = sh2[0] * (1.0f / Hz) - mu * mu;
    float inv = rsqrtf(var + 1e-5f);

    int cbase = tid * 4;
    float4 gv = *(const float4*)(g + cbase);
    float4 bv = *(const float4*)(b + cbase);
    float4 out;
    out.x = (v0 - mu) * inv * gv.x + bv.x;
    out.y = (v1 - mu) * inv * gv.y + bv.y;
    out.z = (v2 - mu) * inv * gv.z + bv.z;
    out.w = (v3 - mu) * inv * gv.w + bv.w;
    *(float4*)(x + off) = out;
}

// --------------------------------- launch ----------------------------------
extern "C" void kernel_launch(void* const* d_in, const int* in_sizes, int n_in,
                              void* d_out, int out_size)
{
    const int*   ids  = (const int*)d_in[0];
    const int*   sp   = (const int*)d_in[1];
    const float* emb  = (const float*)d_in[2];
    const float* Wq   = (const float*)d_in[3];
    const float* bq   = (const float*)d_in[4];
    const float* Wk   = (const float*)d_in[5];
    const float* bk   = (const float*)d_in[6];
    const float* Wv   = (const float*)d_in[7];
    const float* bv   = (const float*)d_in[8];
    const float* Wo   = (const float*)d_in[9];
    const float* bo   = (const float*)d_in[10];
    const float* ln1g = (const float*)d_in[11];
    const float* ln1b = (const float*)d_in[12];
    const float* ln2g = (const float*)d_in[13];
    const float* ln2b = (const float*)d_in[14];
    const float* W1   = (const float*)d_in[15];
    const float* b1   = (const float*)d_in[16];
    const float* W2   = (const float*)d_in[17];
    const float* b2   = (const float*)d_in[18];
    const float* Wf   = (const float*)d_in[19];
    const float* bf   = (const float*)d_in[20];
    float* out = (float*)d_out;

    float *x, *q, *k, *v, *attn, *tmp, *ff;
    cudaGetSymbolAddress((void**)&x,    g_x);
    cudaGetSymbolAddress((void**)&q,    g_q);
    cudaGetSymbolAddress((void**)&k,    g_k);
    cudaGetSymbolAddress((void**)&v,    g_v);
    cudaGetSymbolAddress((void**)&attn, g_attn);
    cudaGetSymbolAddress((void**)&tmp,  g_tmp);
    cudaGetSymbolAddress((void**)&ff,   g_ff);

    cudaFuncSetAttribute(attn_kernel, cudaFuncAttributeMaxDynamicSharedMemorySize, ATTN_SMEM);

    embed_kernel<<<Mz, 256>>>(ids, emb, x);

    for (int l = 0; l < Lz; ++l) {
        size_t wHH = (size_t)l * Hz * Hz;
        gemm_kernel<<<dim3(Hz / BN, Mz / BM), 256>>>(x, Wq + wHH, bq + l * Hz, q,
                                                     Mz, Hz, Hz, 0, sp);
        gemm_kernel<<<dim3(Hz / BN, Mz / BM), 256>>>(x, Wk + wHH, bk + l * Hz, k,
                                                     Mz, Hz, Hz, 0, sp);
        gemm_kernel<<<dim3(Hz / BN, Mz / BM), 256>>>(x, Wv + wHH, bv + l * Hz, v,
                                                     Mz, Hz, Hz, 0, sp);

        attn_kernel<<<dim3(Sz / 64, Bz * NHz), 256, ATTN_SMEM>>>(q, k, v, attn, sp);

        gemm_kernel<<<dim3(Hz / BN, Mz / BM), 256>>>(attn, Wo + wHH, bo + l * Hz, tmp,
                                                     Mz, Hz, Hz, 0, sp);
        add_ln_kernel<<<Mz, 256>>>(x, tmp, ln1g + l * Hz, ln1b + l * Hz);

        gemm_kernel<<<dim3(DFz / BN, Mz / BM), 256>>>(x, W1 + (size_t)l * Hz * DFz,
                                                      b1 + l * DFz, ff,
                                                      Mz, DFz, Hz, 1, sp);
        gemm_kernel<<<dim3(Hz / BN, Mz / BM), 256>>>(ff, W2 + (size_t)l * DFz * Hz,
                                                     b2 + l * Hz, tmp,
                                                     Mz, Hz, DFz, 0, sp);
        add_ln_kernel<<<Mz, 256>>>(x, tmp, ln2g + l * Hz, ln2b + l * Hz);
    }

    gemm_kernel<<<dim3(Vz / BN, Mz / BM), 256>>>(x, Wf, bf, out, Mz, Vz, Hz, 2, sp);
}

// round 2
// speedup vs baseline: 2.4630x; 2.4630x over previous
#include <cuda_runtime.h>
#include <cuda_bf16.h>
#include <math.h>
#include <stdint.h>

// ---------------------------------------------------------------------------
// TidalTransformer: B=4, S=1024, H=1024, NH=16, DK=64, DF=4096, L=4, V=32000
// Round 2: tf32 mma.sync GEMMs (tensor core), flash attention fp32, fused LN.
// ---------------------------------------------------------------------------

#define Bz   4
#define Sz   1024
#define Hz   1024
#define NHz  16
#define DKz  64
#define DFz  4096
#define Lz   4
#define Vz   32000
#define Mz   (Bz * Sz)   // 4096 rows

// ------------------------- scratch (device globals) ------------------------
__device__ float g_x[(size_t)Mz * Hz];
__device__ float g_q[(size_t)Mz * Hz];
__device__ float g_k[(size_t)Mz * Hz];
__device__ float g_v[(size_t)Mz * Hz];
__device__ float g_attn[(size_t)Mz * Hz];
__device__ float g_tmp[(size_t)Mz * Hz];
__device__ float g_ff[(size_t)Mz * DFz];

// ------------------------------- embedding ---------------------------------
__global__ void embed_kernel(const int* __restrict__ ids,
                             const float* __restrict__ emb,
                             float* __restrict__ x)
{
    int row = blockIdx.x;
    int tid = threadIdx.x;
    int id  = ids[row];
    float4 v = *(const float4*)(emb + (size_t)id * Hz + tid * 4);
    v.x *= 32.0f; v.y *= 32.0f; v.z *= 32.0f; v.w *= 32.0f;
    *(float4*)(x + (size_t)row * Hz + tid * 4) = v;
}

// ------------------------------ tf32 GEMM ----------------------------------
// C[M,N] = A[M,K] @ W[K,N] + bias ; op: 0=none, 1=exact GELU, 2=row mask
// Block tile 128x128x16, 8 warps (2m x 4n), warp tile 64x32, mma m16n8k8.

__device__ __forceinline__ float to_tf32(float x) {
    float r;
    asm("cvt.rna.tf32.f32 %0, %1;" : "=f"(r) : "f"(x));
    return r;
}

__device__ __forceinline__ void mma8(float* c, const uint32_t* a, const uint32_t* b) {
    asm volatile(
        "mma.sync.aligned.m16n8k8.row.col.f32.tf32.tf32.f32 "
        "{%0,%1,%2,%3},{%4,%5,%6,%7},{%8,%9},{%0,%1,%2,%3};"
        : "+f"(c[0]), "+f"(c[1]), "+f"(c[2]), "+f"(c[3])
        : "r"(a[0]), "r"(a[1]), "r"(a[2]), "r"(a[3]), "r"(b[0]), "r"(b[1]));
}

#define ASTR 20    // As row stride (floats): row*20 mod 32 is a bank permutation
#define BSTR 136   // Bs row stride (floats): k*136 mod 32 = k*8, conflict-free

__global__ __launch_bounds__(256, 2)
void gemm_tc_kernel(const float* __restrict__ A, const float* __restrict__ W,
                    const float* __restrict__ bias, float* __restrict__ C,
                    int M, int N, int K, int op, const int* __restrict__ start_pos)
{
    __shared__ float As[2][128][ASTR];
    __shared__ float Bs[2][16][BSTR];

    int tid  = threadIdx.x;
    int lane = tid & 31, warp = tid >> 5;
    int wm = warp & 1, wn = warp >> 1;           // 2 x 4 warp grid
    int m0 = blockIdx.y * 128, n0 = blockIdx.x * 128;

    int arow = tid >> 2;            // 0..63 (and +64)
    int acol = (tid & 3) * 4;       // 0,4,8,12
    int brow = warp;                // 0..7 (and +8)
    int bcol = lane * 4;            // 0..124

    const float* Ap0 = A + (size_t)(m0 + arow) * K + acol;
    const float* Ap1 = Ap0 + (size_t)64 * K;
    const float* Wp0 = W + (size_t)brow * N + n0 + bcol;
    const float* Wp1 = Wp0 + (size_t)8 * N;

    float acc[4][4][4];
    #pragma unroll
    for (int i = 0; i < 4; i++)
        #pragma unroll
        for (int j = 0; j < 4; j++)
            #pragma unroll
            for (int r = 0; r < 4; r++) acc[i][j][r] = 0.f;

    float4 av0, av1, bv0, bv1;

    // prologue: fetch tile 0
    av0 = *(const float4*)Ap0;
    av1 = *(const float4*)Ap1;
    bv0 = *(const float4*)Wp0;
    bv1 = *(const float4*)Wp1;
    {
        float4 t;
        t.x = to_tf32(av0.x); t.y = to_tf32(av0.y); t.z = to_tf32(av0.z); t.w = to_tf32(av0.w);
        *(float4*)&As[0][arow][acol] = t;
        t.x = to_tf32(av1.x); t.y = to_tf32(av1.y); t.z = to_tf32(av1.z); t.w = to_tf32(av1.w);
        *(float4*)&As[0][arow + 64][acol] = t;
        t.x = to_tf32(bv0.x); t.y = to_tf32(bv0.y); t.z = to_tf32(bv0.z); t.w = to_tf32(bv0.w);
        *(float4*)&Bs[0][brow][bcol] = t;
        t.x = to_tf32(bv1.x); t.y = to_tf32(bv1.y); t.z = to_tf32(bv1.z); t.w = to_tf32(bv1.w);
        *(float4*)&Bs[0][brow + 8][bcol] = t;
    }
    __syncthreads();

    int kIters = K >> 4;
    for (int it = 0; it < kIters; ++it) {
        int cur = it & 1;
        if (it + 1 < kIters) {
            const float* a0 = Ap0 + (it + 1) * 16;
            const float* a1 = Ap1 + (it + 1) * 16;
            const float* w0 = Wp0 + (size_t)(it + 1) * 16 * N;
            const float* w1 = Wp1 + (size_t)(it + 1) * 16 * N;
            av0 = *(const float4*)a0;
            av1 = *(const float4*)a1;
            bv0 = *(const float4*)w0;
            bv1 = *(const float4*)w1;
        }

        #pragma unroll
        for (int ks = 0; ks < 2; ++ks) {
            int ar = wm * 64 + (lane >> 2);
            int ac = ks * 8 + (lane & 3);
            uint32_t af[4][4], bfr[4][2];
            #pragma unroll
            for (int im = 0; im < 4; im++) {
                af[im][0] = __float_as_uint(As[cur][ar + im * 16    ][ac]);
                af[im][1] = __float_as_uint(As[cur][ar + im * 16 + 8][ac]);
                af[im][2] = __float_as_uint(As[cur][ar + im * 16    ][ac + 4]);
                af[im][3] = __float_as_uint(As[cur][ar + im * 16 + 8][ac + 4]);
            }
            #pragma unroll
            for (int in = 0; in < 4; in++) {
                int bc = wn * 32 + in * 8 + (lane >> 2);
                bfr[in][0] = __float_as_uint(Bs[cur][ks * 8 + (lane & 3)    ][bc]);
                bfr[in][1] = __float_as_uint(Bs[cur][ks * 8 + 4 + (lane & 3)][bc]);
            }
            #pragma unroll
            for (int im = 0; im < 4; im++)
                #pragma unroll
                for (int in = 0; in < 4; in++)
                    mma8(acc[im][in], af[im], bfr[in]);
        }

        if (it + 1 < kIters) {
            int nxt = cur ^ 1;
            float4 t;
            t.x = to_tf32(av0.x); t.y = to_tf32(av0.y); t.z = to_tf32(av0.z); t.w = to_tf32(av0.w);
            *(float4*)&As[nxt][arow][acol] = t;
            t.x = to_tf32(av1.x); t.y = to_tf32(av1.y); t.z = to_tf32(av1.z); t.w = to_tf32(av1.w);
            *(float4*)&As[nxt][arow + 64][acol] = t;
            t.x = to_tf32(bv0.x); t.y = to_tf32(bv0.y); t.z = to_tf32(bv0.z); t.w = to_tf32(bv0.w);
            *(float4*)&Bs[nxt][brow][bcol] = t;
            t.x = to_tf32(bv1.x); t.y = to_tf32(bv1.y); t.z = to_tf32(bv1.z); t.w = to_tf32(bv1.w);
            *(float4*)&Bs[nxt][brow + 8][bcol] = t;
        }
        __syncthreads();
    }

    // epilogue
    int rbase = m0 + wm * 64 + (lane >> 2);
    int cbase = n0 + wn * 32 + ((lane & 3) << 1);
    #pragma unroll
    for (int im = 0; im < 4; im++) {
        #pragma unroll
        for (int half = 0; half < 2; half++) {
            int row = rbase + im * 16 + half * 8;
            bool zero = false;
            if (op == 2) {
                int b = row >> 10;
                zero = (row & 1023) < start_pos[b];
            }
            #pragma unroll
            for (int in = 0; in < 4; in++) {
                int col = cbase + in * 8;
                float v0 = acc[im][in][half * 2 + 0] + bias[col];
                float v1 = acc[im][in][half * 2 + 1] + bias[col + 1];
                if (op == 1) {
                    v0 = 0.5f * v0 * (1.0f + erff(v0 * 0.70710678118654752f));
                    v1 = 0.5f * v1 * (1.0f + erff(v1 * 0.70710678118654752f));
                }
                if (zero) { v0 = 0.f; v1 = 0.f; }
                float2 o; o.x = v0; o.y = v1;
                *(float2*)(C + (size_t)row * N + col) = o;
            }
        }
    }
}

// --------------------------- flash attention -------------------------------
#define ALD 65
#define ATTN_SMEM (3 * 64 * ALD * 4)

__global__ __launch_bounds__(256)
void attn_kernel(const float* __restrict__ Q, const float* __restrict__ Kt,
                 const float* __restrict__ V, float* __restrict__ O,
                 const int* __restrict__ start_pos)
{
    extern __shared__ float sm[];
    float* sq = sm;
    float* sk = sm + 64 * ALD;
    float* sv = sm + 2 * 64 * ALD;

    int tid = threadIdx.x;
    int r = tid >> 2;
    int c = tid & 3;
    int qt = blockIdx.x;
    int bh = blockIdx.y;
    int b = bh >> 4, h = bh & 15;
    int sp = start_pos[b];
    float slope = exp2f(-0.5f * (float)(h + 1));

    size_t base = (size_t)b * Sz * Hz + (size_t)h * DKz;

    for (int i = tid; i < 64 * 16; i += 256) {
        int row = i >> 4, d4 = (i & 15) * 4;
        float4 v = *(const float4*)(Q + base + (size_t)(qt * 64 + row) * Hz + d4);
        sq[row * ALD + d4 + 0] = v.x * 0.125f;
        sq[row * ALD + d4 + 1] = v.y * 0.125f;
        sq[row * ALD + d4 + 2] = v.z * 0.125f;
        sq[row * ALD + d4 + 3] = v.w * 0.125f;
    }

    float m_r = -1e30f, l_r = 0.f;
    float oacc[64];
    #pragma unroll
    for (int d = 0; d < 64; d++) oacc[d] = 0.f;

    int ig = qt * 64 + r;
    int ktmax = (qt * 64 >= sp) ? qt : 15;

    for (int kt = 0; kt <= ktmax; ++kt) {
        __syncthreads();
        for (int i = tid; i < 64 * 16; i += 256) {
            int row = i >> 4, d4 = (i & 15) * 4;
            float4 kv = *(const float4*)(Kt + base + (size_t)(kt * 64 + row) * Hz + d4);
            sk[row * ALD + d4 + 0] = kv.x; sk[row * ALD + d4 + 1] = kv.y;
            sk[row * ALD + d4 + 2] = kv.z; sk[row * ALD + d4 + 3] = kv.w;
            float4 vv = *(const float4*)(V + base + (size_t)(kt * 64 + row) * Hz + d4);
            sv[row * ALD + d4 + 0] = vv.x; sv[row * ALD + d4 + 1] = vv.y;
            sv[row * ALD + d4 + 2] = vv.z; sv[row * ALD + d4 + 3] = vv.w;
        }
        __syncthreads();

        float sc[16];
        #pragma unroll
        for (int jj = 0; jj < 16; jj++) {
            int j = jj * 4 + c;
            float dot = 0.f;
            #pragma unroll
            for (int d = 0; d < 64; d++)
                dot = fmaf(sq[r * ALD + d], sk[j * ALD + d], dot);
            int jg = kt * 64 + j;
            bool ok = (jg <= ig) || (ig < sp) || (jg < sp);
            sc[jj] = ok ? dot + slope * (float)(jg - sp) : -1e9f;
        }

        float tmax = sc[0];
        #pragma unroll
        for (int jj = 1; jj < 16; jj++) tmax = fmaxf(tmax, sc[jj]);
        tmax = fmaxf(tmax, __shfl_xor_sync(0xffffffffu, tmax, 1));
        tmax = fmaxf(tmax, __shfl_xor_sync(0xffffffffu, tmax, 2));

        float m_new = fmaxf(m_r, tmax);
        float scl = expf(m_r - m_new);
        float lsum = 0.f;
        #pragma unroll
        for (int jj = 0; jj < 16; jj++) {
            float p = expf(sc[jj] - m_new);
            sc[jj] = p;
            lsum += p;
        }
        lsum += __shfl_xor_sync(0xffffffffu, lsum, 1);
        lsum += __shfl_xor_sync(0xffffffffu, lsum, 2);
        l_r = l_r * scl + lsum;
        m_r = m_new;

        #pragma unroll
        for (int d = 0; d < 64; d++) oacc[d] *= scl;
        #pragma unroll
        for (int jj = 0; jj < 16; jj++) {
            int kk = jj * 4 + c;
            float p = sc[jj];
            #pragma unroll
            for (int d = 0; d < 64; d++)
                oacc[d] = fmaf(p, sv[kk * ALD + d], oacc[d]);
        }
    }

    #pragma unroll
    for (int d = 0; d < 64; d++) {
        oacc[d] += __shfl_xor_sync(0xffffffffu, oacc[d], 1);
        oacc[d] += __shfl_xor_sync(0xffffffffu, oacc[d], 2);
    }
    float inv = 1.f / l_r;
    size_t orow = base + (size_t)(qt * 64 + r) * Hz;
    #pragma unroll
    for (int jj = 0; jj < 16; jj++) {
        int d = c * 16 + jj;
        O[orow + d] = oacc[d] * inv;
    }
}

// ------------------------ fused residual + layernorm -----------------------
__inline__ __device__ float warp_sum(float v) {
    #pragma unroll
    for (int o = 16; o; o >>= 1) v += __shfl_xor_sync(0xffffffffu, v, o);
    return v;
}

__global__ void add_ln_kernel(float* __restrict__ x, const float* __restrict__ t,
                              const float* __restrict__ g, const float* __restrict__ b)
{
    int row = blockIdx.x;
    int tid = threadIdx.x;
    size_t off = (size_t)row * Hz + tid * 4;

    float4 xv = *(const float4*)(x + off);
    float4 tv = *(const float4*)(t + off);
    float v0 = xv.x + tv.x, v1 = xv.y + tv.y, v2 = xv.z + tv.z, v3 = xv.w + tv.w;

    float s  = v0 + v1 + v2 + v3;
    float s2 = v0 * v0 + v1 * v1 + v2 * v2 + v3 * v3;

    __shared__ float sh1[8], sh2[8];
    int lane = tid & 31, wid = tid >> 5;
    s  = warp_sum(s);
    s2 = warp_sum(s2);
    if (lane == 0) { sh1[wid] = s; sh2[wid] = s2; }
    __syncthreads();
    if (wid == 0) {
        float a = (lane < 8) ? sh1[lane] : 0.f;
        float c = (lane < 8) ? sh2[lane] : 0.f;
        a = warp_sum(a);
        c = warp_sum(c);
        if (lane == 0) { sh1[0] = a; sh2[0] = c; }
    }
    __syncthreads();

    float mu  = sh1[0] * (1.0f / Hz);
    float var = sh2[0] * (1.0f / Hz) - mu * mu;
    float inv = rsqrtf(var + 1e-5f);

    int cbase = tid * 4;
    float4 gv = *(const float4*)(g + cbase);
    float4 bv = *(const float4*)(b + cbase);
    float4 out;
    out.x = (v0 - mu) * inv * gv.x + bv.x;
    out.y = (v1 - mu) * inv * gv.y + bv.y;
    out.z = (v2 - mu) * inv * gv.z + bv.z;
    out.w = (v3 - mu) * inv * gv.w + bv.w;
    *(float4*)(x + off) = out;
}

// --------------------------------- launch ----------------------------------
extern "C" void kernel_launch(void* const* d_in, const int* in_sizes, int n_in,
                              void* d_out, int out_size)
{
    const int*   ids  = (const int*)d_in[0];
    const int*   sp   = (const int*)d_in[1];
    const float* emb  = (const float*)d_in[2];
    const float* Wq   = (const float*)d_in[3];
    const float* bq   = (const float*)d_in[4];
    const float* Wk   = (const float*)d_in[5];
    const float* bk   = (const float*)d_in[6];
    const float* Wv   = (const float*)d_in[7];
    const float* bv   = (const float*)d_in[8];
    const float* Wo   = (const float*)d_in[9];
    const float* bo   = (const float*)d_in[10];
    const float* ln1g = (const float*)d_in[11];
    const float* ln1b = (const float*)d_in[12];
    const float* ln2g = (const float*)d_in[13];
    const float* ln2b = (const float*)d_in[14];
    const float* W1   = (const float*)d_in[15];
    const float* b1   = (const float*)d_in[16];
    const float* W2   = (const float*)d_in[17];
    const float* b2   = (const float*)d_in[18];
    const float* Wf   = (const float*)d_in[19];
    const float* bf   = (const float*)d_in[20];
    float* out = (float*)d_out;

    float *x, *q, *k, *v, *attn, *tmp, *ff;
    cudaGetSymbolAddress((void**)&x,    g_x);
    cudaGetSymbolAddress((void**)&q,    g_q);
    cudaGetSymbolAddress((void**)&k,    g_k);
    cudaGetSymbolAddress((void**)&v,    g_v);
    cudaGetSymbolAddress((void**)&attn, g_attn);
    cudaGetSymbolAddress((void**)&tmp,  g_tmp);
    cudaGetSymbolAddress((void**)&ff,   g_ff);

    cudaFuncSetAttribute(attn_kernel, cudaFuncAttributeMaxDynamicSharedMemorySize, ATTN_SMEM);

    embed_kernel<<<Mz, 256>>>(ids, emb, x);

    for (int l = 0; l < Lz; ++l) {
        size_t wHH = (size_t)l * Hz * Hz;
        gemm_tc_kernel<<<dim3(Hz / 128, Mz / 128), 256>>>(x, Wq + wHH, bq + l * Hz, q,
                                                          Mz, Hz, Hz, 0, sp);
        gemm_tc_kernel<<<dim3(Hz / 128, Mz / 128), 256>>>(x, Wk + wHH, bk + l * Hz, k,
                                                          Mz, Hz, Hz, 0, sp);
        gemm_tc_kernel<<<dim3(Hz / 128, Mz / 128), 256>>>(x, Wv + wHH, bv + l * Hz, v,
                                                          Mz, Hz, Hz, 0, sp);

        attn_kernel<<<dim3(Sz / 64, Bz * NHz), 256, ATTN_SMEM>>>(q, k, v, attn, sp);

        gemm_tc_kernel<<<dim3(Hz / 128, Mz / 128), 256>>>(attn, Wo + wHH, bo + l * Hz, tmp,
                                                          Mz, Hz, Hz, 0, sp);
        add_ln_kernel<<<Mz, 256>>>(x, tmp, ln1g + l * Hz, ln1b + l * Hz);

        gemm_tc_kernel<<<dim3(DFz / 128, Mz / 128), 256>>>(x, W1 + (size_t)l * Hz * DFz,
                                                           b1 + l * DFz, ff,
                                                           Mz, DFz, Hz, 1, sp);
        gemm_tc_kernel<<<dim3(Hz / 128, Mz / 128), 256>>>(ff, W2 + (size_t)l * DFz * Hz,
                                                          b2 + l * Hz, tmp,
                                                          Mz, Hz, DFz, 0, sp);
        add_ln_kernel<<<Mz, 256>>>(x, tmp, ln2g + l * Hz, ln2b + l * Hz);
    }

    gemm_tc_kernel<<<dim3(Vz / 128, Mz / 128), 256>>>(x, Wf, bf, out, Mz, Vz, Hz, 2, sp);
}

// round 3
// speedup vs baseline: 2.7418x; 1.1132x over previous
#include <cuda_runtime.h>
#include <cuda_bf16.h>
#include <math.h>
#include <stdint.h>

// ---------------------------------------------------------------------------
// TidalTransformer: B=4, S=1024, H=1024, NH=16, DK=64, DF=4096, L=4, V=32000
// Round 3: pre-converted tf32 weights + cp.async 3-stage pipelined mma GEMM,
//          fused QKV projection, flash attention fp32, fused LN.
// ---------------------------------------------------------------------------

#define Bz   4
#define Sz   1024
#define Hz   1024
#define NHz  16
#define DKz  64
#define DFz  4096
#define Lz   4
#define Vz   32000
#define Mz   (Bz * Sz)   // 4096 rows
#define QKVN 3072

// ------------------------- scratch (device globals) ------------------------
__device__ float g_x   [(size_t)Mz * Hz];      // fp32 residual stream
__device__ float g_xc  [(size_t)Mz * Hz];      // tf32-rounded copy of x
__device__ float g_qkv [(size_t)Mz * QKVN];    // fused q|k|v (fp32)
__device__ float g_attnc[(size_t)Mz * Hz];     // attention out (tf32-rounded)
__device__ float g_tmp [(size_t)Mz * Hz];      // gemm out (fp32)
__device__ float g_ffc [(size_t)Mz * DFz];     // gelu out (tf32-rounded)

// tf32 weight pool
#define OFF_QKV 0
#define OFF_WO  ((size_t)12582912)             // 4*1024*3072
#define OFF_W1  ((size_t)16777216)
#define OFF_W2  ((size_t)33554432)
#define OFF_WF  ((size_t)50331648)
__device__ float g_w[(size_t)83099648];        // 332 MB
__device__ float g_bqkv[Lz * QKVN];

__device__ __forceinline__ float to_tf32(float x) {
    float r;
    asm("cvt.rna.tf32.f32 %0, %1;" : "=f"(r) : "f"(x));
    return r;
}

// ----------------------------- converters ----------------------------------
__global__ void cvt4_kernel(const float* __restrict__ s, float* __restrict__ d, int n4)
{
    int i = blockIdx.x * 256 + threadIdx.x;
    if (i < n4) {
        float4 v = ((const float4*)s)[i];
        v.x = to_tf32(v.x); v.y = to_tf32(v.y); v.z = to_tf32(v.z); v.w = to_tf32(v.w);
        ((float4*)d)[i] = v;
    }
}

__global__ void cvt_qkv_kernel(const float* __restrict__ Wq, const float* __restrict__ Wk,
                               const float* __restrict__ Wv, float* __restrict__ dst)
{
    size_t i = (size_t)blockIdx.x * 256 + threadIdx.x;   // Lz*Hz*QKVN total
    int n = (int)(i % QKVN);
    size_t lk = i / QKVN;                                // l*H + k
    float v;
    if (n < 1024)       v = Wq[lk * 1024 + n];
    else if (n < 2048)  v = Wk[lk * 1024 + n - 1024];
    else                v = Wv[lk * 1024 + n - 2048];
    dst[i] = to_tf32(v);
}

__global__ void cvt_bias_kernel(const float* __restrict__ bq, const float* __restrict__ bk,
                                const float* __restrict__ bv, float* __restrict__ dst)
{
    int i = blockIdx.x * 256 + threadIdx.x;              // Lz*QKVN
    int n = i % QKVN, l = i / QKVN;
    float v;
    if (n < 1024)       v = bq[l * 1024 + n];
    else if (n < 2048)  v = bk[l * 1024 + n - 1024];
    else                v = bv[l * 1024 + n - 2048];
    dst[i] = v;
}

// ------------------------------- embedding ---------------------------------
__global__ void embed_kernel(const int* __restrict__ ids,
                             const float* __restrict__ emb,
                             float* __restrict__ x, float* __restrict__ xc)
{
    int row = blockIdx.x;
    int tid = threadIdx.x;
    int id  = ids[row];
    float4 v = *(const float4*)(emb + (size_t)id * Hz + tid * 4);
    v.x *= 32.0f; v.y *= 32.0f; v.z *= 32.0f; v.w *= 32.0f;
    *(float4*)(x + (size_t)row * Hz + tid * 4) = v;
    float4 c;
    c.x = to_tf32(v.x); c.y = to_tf32(v.y); c.z = to_tf32(v.z); c.w = to_tf32(v.w);
    *(float4*)(xc + (size_t)row * Hz + tid * 4) = c;
}

// ---------------------- tf32 GEMM, cp.async pipelined -----------------------
// Block 128x128x32, 3-stage cp.async, 8 warps (2m x 4n), warp 64x32, m16n8k8.
// Inputs A and W must already be tf32-rounded. op: 0=none 1=GELU(+tf32 out) 2=rowmask

#define ASTR 36
#define BSTR 136
#define AS_STAGE (128 * ASTR)   // 4608 floats
#define BS_STAGE (32 * BSTR)    // 4352 floats
#define GEMM_SMEM (3 * (AS_STAGE + BS_STAGE) * 4)   // 107520 bytes

__device__ __forceinline__ void cpasync16(uint32_t dst, const void* src) {
    asm volatile("cp.async.cg.shared.global [%0], [%1], 16;" :: "r"(dst), "l"(src));
}

__device__ __forceinline__ void mma8(float* c, const uint32_t* a, const uint32_t* b) {
    asm volatile(
        "mma.sync.aligned.m16n8k8.row.col.f32.tf32.tf32.f32 "
        "{%0,%1,%2,%3},{%4,%5,%6,%7},{%8,%9},{%0,%1,%2,%3};"
        : "+f"(c[0]), "+f"(c[1]), "+f"(c[2]), "+f"(c[3])
        : "r"(a[0]), "r"(a[1]), "r"(a[2]), "r"(a[3]), "r"(b[0]), "r"(b[1]));
}

__global__ __launch_bounds__(256, 2)
void gemm_tc_kernel(const float* __restrict__ A, const float* __restrict__ W,
                    const float* __restrict__ bias, float* __restrict__ C,
                    int M, int N, int K, int op, const int* __restrict__ start_pos)
{
    extern __shared__ float sm_[];
    float* As = sm_;                    // [3][128][36]
    float* Bs = sm_ + 3 * AS_STAGE;     // [3][32][136]

    int tid = threadIdx.x, lane = tid & 31, warp = tid >> 5;
    int wm = warp & 1, wn = warp >> 1;
    int m0 = blockIdx.y * 128, n0 = blockIdx.x * 128;

    const float* aG[4]; uint32_t asOff[4];
    const float* bG[4]; uint32_t bsOff[4];
    #pragma unroll
    for (int i = 0; i < 4; i++) {
        int idx = tid + i * 256;
        int r = idx >> 3, c4 = (idx & 7) * 4;
        aG[i] = A + (size_t)(m0 + r) * K + c4;
        asOff[i] = (uint32_t)(r * ASTR + c4) * 4;
        int k = idx >> 5, n4 = (idx & 31) * 4;
        bG[i] = W + (size_t)k * N + n0 + n4;
        bsOff[i] = (uint32_t)(k * BSTR + n4) * 4;
    }
    uint32_t asBase = (uint32_t)__cvta_generic_to_shared(As);
    uint32_t bsBase = (uint32_t)__cvta_generic_to_shared(Bs);

    float acc[4][4][4];
    #pragma unroll
    for (int i = 0; i < 4; i++)
        #pragma unroll
        for (int j = 0; j < 4; j++)
            #pragma unroll
            for (int r = 0; r < 4; r++) acc[i][j][r] = 0.f;

    int KT = K >> 5;

    // prologue: stages 0,1
    #pragma unroll
    for (int s = 0; s < 2; s++) {
        int kk = s * 32;
        #pragma unroll
        for (int i = 0; i < 4; i++)
            cpasync16(asBase + s * (AS_STAGE * 4) + asOff[i], aG[i] + kk);
        #pragma unroll
        for (int i = 0; i < 4; i++)
            cpasync16(bsBase + s * (BS_STAGE * 4) + bsOff[i], bG[i] + (size_t)kk * N);
        asm volatile("cp.async.commit_group;");
    }

    int aoff = (wm * 64 + (lane >> 2)) * ASTR + (lane & 3);
    int boff = (lane & 3) * BSTR + wn * 32 + (lane >> 2);

    for (int kt = 0; kt < KT; ++kt) {
        asm volatile("cp.async.wait_group 1;" ::: "memory");
        __syncthreads();

        if (kt + 2 < KT) {
            int s = (kt + 2) % 3;
            int kk = (kt + 2) * 32;
            #pragma unroll
            for (int i = 0; i < 4; i++)
                cpasync16(asBase + s * (AS_STAGE * 4) + asOff[i], aG[i] + kk);
            #pragma unroll
            for (int i = 0; i < 4; i++)
                cpasync16(bsBase + s * (BS_STAGE * 4) + bsOff[i], bG[i] + (size_t)kk * N);
        }
        asm volatile("cp.async.commit_group;");

        const float* aP = As + (kt % 3) * AS_STAGE + aoff;
        const float* bP = Bs + (kt % 3) * BS_STAGE + boff;

        #pragma unroll
        for (int ks = 0; ks < 4; ++ks) {
            uint32_t af[4][4], bfr[4][2];
            #pragma unroll
            for (int im = 0; im < 4; im++) {
                af[im][0] = __float_as_uint(aP[(im * 16)     * ASTR + ks * 8]);
                af[im][1] = __float_as_uint(aP[(im * 16 + 8) * ASTR + ks * 8]);
                af[im][2] = __float_as_uint(aP[(im * 16)     * ASTR + ks * 8 + 4]);
                af[im][3] = __float_as_uint(aP[(im * 16 + 8) * ASTR + ks * 8 + 4]);
            }
            #pragma unroll
            for (int in = 0; in < 4; in++) {
                bfr[in][0] = __float_as_uint(bP[(ks * 8)     * BSTR + in * 8]);
                bfr[in][1] = __float_as_uint(bP[(ks * 8 + 4) * BSTR + in * 8]);
            }
            #pragma unroll
            for (int im = 0; im < 4; im++)
                #pragma unroll
                for (int in = 0; in < 4; in++)
                    mma8(acc[im][in], af[im], bfr[in]);
        }
    }

    // epilogue
    int rbase = m0 + wm * 64 + (lane >> 2);
    int cbase = n0 + wn * 32 + ((lane & 3) << 1);
    #pragma unroll
    for (int im = 0; im < 4; im++) {
        #pragma unroll
        for (int half = 0; half < 2; half++) {
            int row = rbase + im * 16 + half * 8;
            bool zero = false;
            if (op == 2) {
                int b = row >> 10;
                zero = (row & 1023) < start_pos[b];
            }
            #pragma unroll
            for (int in = 0; in < 4; in++) {
                int col = cbase + in * 8;
                float v0 = acc[im][in][half * 2 + 0] + bias[col];
                float v1 = acc[im][in][half * 2 + 1] + bias[col + 1];
                if (op == 1) {
                    v0 = 0.5f * v0 * (1.0f + erff(v0 * 0.70710678118654752f));
                    v1 = 0.5f * v1 * (1.0f + erff(v1 * 0.70710678118654752f));
                    v0 = to_tf32(v0); v1 = to_tf32(v1);
                }
                if (zero) { v0 = 0.f; v1 = 0.f; }
                float2 o; o.x = v0; o.y = v1;
                *(float2*)(C + (size_t)row * N + col) = o;
            }
        }
    }
}

// --------------------------- flash attention -------------------------------
#define ALD 65
#define ATTN_SMEM (3 * 64 * ALD * 4)

__global__ __launch_bounds__(256)
void attn_kernel(const float* __restrict__ QKV, float* __restrict__ O,
                 const int* __restrict__ start_pos)
{
    extern __shared__ float sm[];
    float* sq = sm;
    float* sk = sm + 64 * ALD;
    float* sv = sm + 2 * 64 * ALD;

    int tid = threadIdx.x;
    int r = tid >> 2;
    int c = tid & 3;
    int qt = blockIdx.x;
    int bh = blockIdx.y;
    int b = bh >> 4, h = bh & 15;
    int sp = start_pos[b];
    float slope = exp2f(-0.5f * (float)(h + 1));

    const float* Qb = QKV + h * 64;
    const float* Kb = QKV + 1024 + h * 64;
    const float* Vb = QKV + 2048 + h * 64;
    int brow = b * Sz;

    for (int i = tid; i < 64 * 16; i += 256) {
        int row = i >> 4, d4 = (i & 15) * 4;
        float4 v = *(const float4*)(Qb + (size_t)(brow + qt * 64 + row) * QKVN + d4);
        sq[row * ALD + d4 + 0] = v.x * 0.125f;
        sq[row * ALD + d4 + 1] = v.y * 0.125f;
        sq[row * ALD + d4 + 2] = v.z * 0.125f;
        sq[row * ALD + d4 + 3] = v.w * 0.125f;
    }

    float m_r = -1e30f, l_r = 0.f;
    float oacc[64];
    #pragma unroll
    for (int d = 0; d < 64; d++) oacc[d] = 0.f;

    int ig = qt * 64 + r;
    int ktmax = (qt * 64 >= sp) ? qt : 15;

    for (int kt = 0; kt <= ktmax; ++kt) {
        __syncthreads();
        for (int i = tid; i < 64 * 16; i += 256) {
            int row = i >> 4, d4 = (i & 15) * 4;
            float4 kv = *(const float4*)(Kb + (size_t)(brow + kt * 64 + row) * QKVN + d4);
            sk[row * ALD + d4 + 0] = kv.x; sk[row * ALD + d4 + 1] = kv.y;
            sk[row * ALD + d4 + 2] = kv.z; sk[row * ALD + d4 + 3] = kv.w;
            float4 vv = *(const float4*)(Vb + (size_t)(brow + kt * 64 + row) * QKVN + d4);
            sv[row * ALD + d4 + 0] = vv.x; sv[row * ALD + d4 + 1] = vv.y;
            sv[row * ALD + d4 + 2] = vv.z; sv[row * ALD + d4 + 3] = vv.w;
        }
        __syncthreads();

        float sc[16];
        #pragma unroll
        for (int jj = 0; jj < 16; jj++) {
            int j = jj * 4 + c;
            float dot = 0.f;
            #pragma unroll
            for (int d = 0; d < 64; d++)
                dot = fmaf(sq[r * ALD + d], sk[j * ALD + d], dot);
            int jg = kt * 64 + j;
            bool ok = (jg <= ig) || (ig < sp) || (jg < sp);
            sc[jj] = ok ? dot + slope * (float)(jg - sp) : -1e9f;
        }

        float tmax = sc[0];
        #pragma unroll
        for (int jj = 1; jj < 16; jj++) tmax = fmaxf(tmax, sc[jj]);
        tmax = fmaxf(tmax, __shfl_xor_sync(0xffffffffu, tmax, 1));
        tmax = fmaxf(tmax, __shfl_xor_sync(0xffffffffu, tmax, 2));

        float m_new = fmaxf(m_r, tmax);
        float scl = expf(m_r - m_new);
        float lsum = 0.f;
        #pragma unroll
        for (int jj = 0; jj < 16; jj++) {
            float p = expf(sc[jj] - m_new);
            sc[jj] = p;
            lsum += p;
        }
        lsum += __shfl_xor_sync(0xffffffffu, lsum, 1);
        lsum += __shfl_xor_sync(0xffffffffu, lsum, 2);
        l_r = l_r * scl + lsum;
        m_r = m_new;

        #pragma unroll
        for (int d = 0; d < 64; d++) oacc[d] *= scl;
        #pragma unroll
        for (int jj = 0; jj < 16; jj++) {
            int kk = jj * 4 + c;
            float p = sc[jj];
            #pragma unroll
            for (int d = 0; d < 64; d++)
                oacc[d] = fmaf(p, sv[kk * ALD + d], oacc[d]);
        }
    }

    #pragma unroll
    for (int d = 0; d < 64; d++) {
        oacc[d] += __shfl_xor_sync(0xffffffffu, oacc[d], 1);
        oacc[d] += __shfl_xor_sync(0xffffffffu, oacc[d], 2);
    }
    float inv = 1.f / l_r;
    size_t orow = (size_t)(brow + qt * 64 + r) * Hz + h * 64;
    #pragma unroll
    for (int jj = 0; jj < 16; jj++) {
        int d = c * 16 + jj;
        O[orow + d] = to_tf32(oacc[d] * inv);
    }
}

// ------------------------ fused residual + layernorm -----------------------
__inline__ __device__ float warp_sum(float v) {
    #pragma unroll
    for (int o = 16; o; o >>= 1) v += __shfl_xor_sync(0xffffffffu, v, o);
    return v;
}

__global__ void add_ln_kernel(float* __restrict__ x, float* __restrict__ xc,
                              const float* __restrict__ t,
                              const float* __restrict__ g, const float* __restrict__ b)
{
    int row = blockIdx.x;
    int tid = threadIdx.x;
    size_t off = (size_t)row * Hz + tid * 4;

    float4 xv = *(const float4*)(x + off);
    float4 tv = *(const float4*)(t + off);
    float v0 = xv.x + tv.x, v1 = xv.y + tv.y, v2 = xv.z + tv.z, v3 = xv.w + tv.w;

    float s  = v0 + v1 + v2 + v3;
    float s2 = v0 * v0 + v1 * v1 + v2 * v2 + v3 * v3;

    __shared__ float sh1[8], sh2[8];
    int lane = tid & 31, wid = tid >> 5;
    s  = warp_sum(s);
    s2 = warp_sum(s2);
    if (lane == 0) { sh1[wid] = s; sh2[wid] = s2; }
    __syncthreads();
    if (wid == 0) {
        float a = (lane < 8) ? sh1[lane] : 0.f;
        float c = (lane < 8) ? sh2[lane] : 0.f;
        a = warp_sum(a);
        c = warp_sum(c);
        if (lane == 0) { sh1[0] = a; sh2[0] = c; }
    }
    __syncthreads();

    float mu  = sh1[0] * (1.0f / Hz);
    float var = sh2[0] * (1.0f / Hz) - mu * mu;
    float inv = rsqrtf(var + 1e-5f);

    int cbase = tid * 4;
    float4 gv = *(const float4*)(g + cbase);
    float4 bv = *(const float4*)(b + cbase);
    float4 out;
    out.x = (v0 - mu) * inv * gv.x + bv.x;
    out.y = (v1 - mu) * inv * gv.y + bv.y;
    out.z = (v2 - mu) * inv * gv.z + bv.z;
    out.w = (v3 - mu) * inv * gv.w + bv.w;
    *(float4*)(x + off) = out;
    float4 oc;
    oc.x = to_tf32(out.x); oc.y = to_tf32(out.y);
    oc.z = to_tf32(out.z); oc.w = to_tf32(out.w);
    *(float4*)(xc + off) = oc;
}

// --------------------------------- launch ----------------------------------
extern "C" void kernel_launch(void* const* d_in, const int* in_sizes, int n_in,
                              void* d_out, int out_size)
{
    const int*   ids  = (const int*)d_in[0];
    const int*   sp   = (const int*)d_in[1];
    const float* emb  = (const float*)d_in[2];
    const float* Wq   = (const float*)d_in[3];
    const float* bq   = (const float*)d_in[4];
    const float* Wk   = (const float*)d_in[5];
    const float* bk   = (const float*)d_in[6];
    const float* Wv   = (const float*)d_in[7];
    const float* bv   = (const float*)d_in[8];
    const float* Wo   = (const float*)d_in[9];
    const float* bo   = (const float*)d_in[10];
    const float* ln1g = (const float*)d_in[11];
    const float* ln1b = (const float*)d_in[12];
    const float* ln2g = (const float*)d_in[13];
    const float* ln2b = (const float*)d_in[14];
    const float* W1   = (const float*)d_in[15];
    const float* b1   = (const float*)d_in[16];
    const float* W2   = (const float*)d_in[17];
    const float* b2   = (const float*)d_in[18];
    const float* Wf   = (const float*)d_in[19];
    const float* bf   = (const float*)d_in[20];
    float* out = (float*)d_out;

    float *x, *xc, *qkv, *attnc, *tmp, *ffc, *w, *bqkv;
    cudaGetSymbolAddress((void**)&x,     g_x);
    cudaGetSymbolAddress((void**)&xc,    g_xc);
    cudaGetSymbolAddress((void**)&qkv,   g_qkv);
    cudaGetSymbolAddress((void**)&attnc, g_attnc);
    cudaGetSymbolAddress((void**)&tmp,   g_tmp);
    cudaGetSymbolAddress((void**)&ffc,   g_ffc);
    cudaGetSymbolAddress((void**)&w,     g_w);
    cudaGetSymbolAddress((void**)&bqkv,  g_bqkv);

    cudaFuncSetAttribute(attn_kernel, cudaFuncAttributeMaxDynamicSharedMemorySize, ATTN_SMEM);
    cudaFuncSetAttribute(gemm_tc_kernel, cudaFuncAttributeMaxDynamicSharedMemorySize, GEMM_SMEM);

    // ---- weight conversion (tf32) ----
    cvt_qkv_kernel<<<(Lz * Hz * QKVN) / 256, 256>>>(Wq, Wk, Wv, w + OFF_QKV);
    cvt_bias_kernel<<<(Lz * QKVN) / 256, 256>>>(bq, bk, bv, bqkv);
    cvt4_kernel<<<(Lz * Hz * Hz / 4) / 256, 256>>>(Wo, w + OFF_WO, Lz * Hz * Hz / 4);
    cvt4_kernel<<<(Lz * Hz * DFz / 4) / 256, 256>>>(W1, w + OFF_W1, Lz * Hz * DFz / 4);
    cvt4_kernel<<<(Lz * DFz * Hz / 4) / 256, 256>>>(W2, w + OFF_W2, Lz * DFz * Hz / 4);
    cvt4_kernel<<<(Hz * Vz / 4) / 256, 256>>>(Wf, w + OFF_WF, Hz * Vz / 4);

    embed_kernel<<<Mz, 256>>>(ids, emb, x, xc);

    for (int l = 0; l < Lz; ++l) {
        gemm_tc_kernel<<<dim3(QKVN / 128, Mz / 128), 256, GEMM_SMEM>>>(
            xc, w + OFF_QKV + (size_t)l * Hz * QKVN, bqkv + l * QKVN, qkv,
            Mz, QKVN, Hz, 0, sp);

        attn_kernel<<<dim3(Sz / 64, Bz * NHz), 256, ATTN_SMEM>>>(qkv, attnc, sp);

        gemm_tc_kernel<<<dim3(Hz / 128, Mz / 128), 256, GEMM_SMEM>>>(
            attnc, w + OFF_WO + (size_t)l * Hz * Hz, bo + l * Hz, tmp,
            Mz, Hz, Hz, 0, sp);
        add_ln_kernel<<<Mz, 256>>>(x, xc, tmp, ln1g + l * Hz, ln1b + l * Hz);

        gemm_tc_kernel<<<dim3(DFz / 128, Mz / 128), 256, GEMM_SMEM>>>(
            xc, w + OFF_W1 + (size_t)l * Hz * DFz, b1 + l * DFz, ffc,
            Mz, DFz, Hz, 1, sp);
        gemm_tc_kernel<<<dim3(Hz / 128, Mz / 128), 256, GEMM_SMEM>>>(
            ffc, w + OFF_W2 + (size_t)l * DFz * Hz, b2 + l * Hz, tmp,
            Mz, Hz, DFz, 0, sp);
        add_ln_kernel<<<Mz, 256>>>(x, xc, tmp, ln2g + l * Hz, ln2b + l * Hz);
    }

    gemm_tc_kernel<<<dim3(Vz / 128, Mz / 128), 256, GEMM_SMEM>>>(
        xc, w + OFF_WF, bf, out, Mz, Vz, Hz, 2, sp);
}

// round 4
// speedup vs baseline: 4.1126x; 1.5000x over previous
#include <cuda_runtime.h>
#include <cuda_bf16.h>
#include <math.h>
#include <stdint.h>

// ---------------------------------------------------------------------------
// TidalTransformer: B=4, S=1024, H=1024, NH=16, DK=64, DF=4096, L=4, V=32000
// Round 4: tensor-core flash attention (split-Q 2-pass tf32 QK, tf32 PV),
//          tf32 cp.async GEMMs, fused QKV, fused LN.
// ---------------------------------------------------------------------------

#define Bz   4
#define Sz   1024
#define Hz   1024
#define NHz  16
#define DKz  64
#define DFz  4096
#define Lz   4
#define Vz   32000
#define Mz   (Bz * Sz)
#define QKVN 3072

// ------------------------- scratch (device globals) ------------------------
__device__ float g_x   [(size_t)Mz * Hz];
__device__ float g_xc  [(size_t)Mz * Hz];
__device__ float g_qkv [(size_t)Mz * QKVN];
__device__ float g_attnc[(size_t)Mz * Hz];
__device__ float g_tmp [(size_t)Mz * Hz];
__device__ float g_ffc [(size_t)Mz * DFz];

#define OFF_QKV 0
#define OFF_WO  ((size_t)12582912)
#define OFF_W1  ((size_t)16777216)
#define OFF_W2  ((size_t)33554432)
#define OFF_WF  ((size_t)50331648)
__device__ float g_w[(size_t)83099648];
__device__ float g_bqkv[Lz * QKVN];

__device__ __forceinline__ float to_tf32(float x) {
    float r;
    asm("cvt.rna.tf32.f32 %0, %1;" : "=f"(r) : "f"(x));
    return r;
}

// ----------------------------- converters ----------------------------------
__global__ void cvt4_kernel(const float* __restrict__ s, float* __restrict__ d, int n4)
{
    int i = blockIdx.x * 256 + threadIdx.x;
    if (i < n4) {
        float4 v = ((const float4*)s)[i];
        v.x = to_tf32(v.x); v.y = to_tf32(v.y); v.z = to_tf32(v.z); v.w = to_tf32(v.w);
        ((float4*)d)[i] = v;
    }
}

__global__ void cvt_qkv_kernel(const float* __restrict__ Wq, const float* __restrict__ Wk,
                               const float* __restrict__ Wv, float* __restrict__ dst)
{
    size_t i = (size_t)blockIdx.x * 256 + threadIdx.x;
    int n = (int)(i % QKVN);
    size_t lk = i / QKVN;
    float v;
    if (n < 1024)       v = Wq[lk * 1024 + n];
    else if (n < 2048)  v = Wk[lk * 1024 + n - 1024];
    else                v = Wv[lk * 1024 + n - 2048];
    dst[i] = to_tf32(v);
}

__global__ void cvt_bias_kernel(const float* __restrict__ bq, const float* __restrict__ bk,
                                const float* __restrict__ bv, float* __restrict__ dst)
{
    int i = blockIdx.x * 256 + threadIdx.x;
    int n = i % QKVN, l = i / QKVN;
    float v;
    if (n < 1024)       v = bq[l * 1024 + n];
    else if (n < 2048)  v = bk[l * 1024 + n - 1024];
    else                v = bv[l * 1024 + n - 2048];
    dst[i] = v;
}

// ------------------------------- embedding ---------------------------------
__global__ void embed_kernel(const int* __restrict__ ids,
                             const float* __restrict__ emb,
                             float* __restrict__ x, float* __restrict__ xc)
{
    int row = blockIdx.x;
    int tid = threadIdx.x;
    int id  = ids[row];
    float4 v = *(const float4*)(emb + (size_t)id * Hz + tid * 4);
    v.x *= 32.0f; v.y *= 32.0f; v.z *= 32.0f; v.w *= 32.0f;
    *(float4*)(x + (size_t)row * Hz + tid * 4) = v;
    float4 c;
    c.x = to_tf32(v.x); c.y = to_tf32(v.y); c.z = to_tf32(v.z); c.w = to_tf32(v.w);
    *(float4*)(xc + (size_t)row * Hz + tid * 4) = c;
}

// ---------------------- tf32 GEMM, cp.async pipelined -----------------------
#define ASTR 36
#define BSTR 136
#define AS_STAGE (128 * ASTR)
#define BS_STAGE (32 * BSTR)
#define GEMM_SMEM (3 * (AS_STAGE + BS_STAGE) * 4)

__device__ __forceinline__ void cpasync16(uint32_t dst, const void* src) {
    asm volatile("cp.async.cg.shared.global [%0], [%1], 16;" :: "r"(dst), "l"(src));
}

__device__ __forceinline__ void mma8(float* c, const uint32_t* a, const uint32_t* b) {
    asm volatile(
        "mma.sync.aligned.m16n8k8.row.col.f32.tf32.tf32.f32 "
        "{%0,%1,%2,%3},{%4,%5,%6,%7},{%8,%9},{%0,%1,%2,%3};"
        : "+f"(c[0]), "+f"(c[1]), "+f"(c[2]), "+f"(c[3])
        : "r"(a[0]), "r"(a[1]), "r"(a[2]), "r"(a[3]), "r"(b[0]), "r"(b[1]));
}

__global__ __launch_bounds__(256, 2)
void gemm_tc_kernel(const float* __restrict__ A, const float* __restrict__ W,
                    const float* __restrict__ bias, float* __restrict__ C,
                    int M, int N, int K, int op, const int* __restrict__ start_pos)
{
    extern __shared__ float sm_[];
    float* As = sm_;
    float* Bs = sm_ + 3 * AS_STAGE;

    int tid = threadIdx.x, lane = tid & 31, warp = tid >> 5;
    int wm = warp & 1, wn = warp >> 1;
    int m0 = blockIdx.y * 128, n0 = blockIdx.x * 128;

    const float* aG[4]; uint32_t asOff[4];
    const float* bG[4]; uint32_t bsOff[4];
    #pragma unroll
    for (int i = 0; i < 4; i++) {
        int idx = tid + i * 256;
        int r = idx >> 3, c4 = (idx & 7) * 4;
        aG[i] = A + (size_t)(m0 + r) * K + c4;
        asOff[i] = (uint32_t)(r * ASTR + c4) * 4;
        int k = idx >> 5, n4 = (idx & 31) * 4;
        bG[i] = W + (size_t)k * N + n0 + n4;
        bsOff[i] = (uint32_t)(k * BSTR + n4) * 4;
    }
    uint32_t asBase = (uint32_t)__cvta_generic_to_shared(As);
    uint32_t bsBase = (uint32_t)__cvta_generic_to_shared(Bs);

    float acc[4][4][4];
    #pragma unroll
    for (int i = 0; i < 4; i++)
        #pragma unroll
        for (int j = 0; j < 4; j++)
            #pragma unroll
            for (int r = 0; r < 4; r++) acc[i][j][r] = 0.f;

    int KT = K >> 5;

    #pragma unroll
    for (int s = 0; s < 2; s++) {
        int kk = s * 32;
        #pragma unroll
        for (int i = 0; i < 4; i++)
            cpasync16(asBase + s * (AS_STAGE * 4) + asOff[i], aG[i] + kk);
        #pragma unroll
        for (int i = 0; i < 4; i++)
            cpasync16(bsBase + s * (BS_STAGE * 4) + bsOff[i], bG[i] + (size_t)kk * N);
        asm volatile("cp.async.commit_group;");
    }

    int aoff = (wm * 64 + (lane >> 2)) * ASTR + (lane & 3);
    int boff = (lane & 3) * BSTR + wn * 32 + (lane >> 2);

    for (int kt = 0; kt < KT; ++kt) {
        asm volatile("cp.async.wait_group 1;" ::: "memory");
        __syncthreads();

        if (kt + 2 < KT) {
            int s = (kt + 2) % 3;
            int kk = (kt + 2) * 32;
            #pragma unroll
            for (int i = 0; i < 4; i++)
                cpasync16(asBase + s * (AS_STAGE * 4) + asOff[i], aG[i] + kk);
            #pragma unroll
            for (int i = 0; i < 4; i++)
                cpasync16(bsBase + s * (BS_STAGE * 4) + bsOff[i], bG[i] + (size_t)kk * N);
        }
        asm volatile("cp.async.commit_group;");

        const float* aP = As + (kt % 3) * AS_STAGE + aoff;
        const float* bP = Bs + (kt % 3) * BS_STAGE + boff;

        #pragma unroll
        for (int ks = 0; ks < 4; ++ks) {
            uint32_t af[4][4], bfr[4][2];
            #pragma unroll
            for (int im = 0; im < 4; im++) {
                af[im][0] = __float_as_uint(aP[(im * 16)     * ASTR + ks * 8]);
                af[im][1] = __float_as_uint(aP[(im * 16 + 8) * ASTR + ks * 8]);
                af[im][2] = __float_as_uint(aP[(im * 16)     * ASTR + ks * 8 + 4]);
                af[im][3] = __float_as_uint(aP[(im * 16 + 8) * ASTR + ks * 8 + 4]);
            }
            #pragma unroll
            for (int in = 0; in < 4; in++) {
                bfr[in][0] = __float_as_uint(bP[(ks * 8)     * BSTR + in * 8]);
                bfr[in][1] = __float_as_uint(bP[(ks * 8 + 4) * BSTR + in * 8]);
            }
            #pragma unroll
            for (int im = 0; im < 4; im++)
                #pragma unroll
                for (int in = 0; in < 4; in++)
                    mma8(acc[im][in], af[im], bfr[in]);
        }
    }

    int rbase = m0 + wm * 64 + (lane >> 2);
    int cbase = n0 + wn * 32 + ((lane & 3) << 1);
    #pragma unroll
    for (int im = 0; im < 4; im++) {
        #pragma unroll
        for (int half = 0; half < 2; half++) {
            int row = rbase + im * 16 + half * 8;
            bool zero = false;
            if (op == 2) {
                int b = row >> 10;
                zero = (row & 1023) < start_pos[b];
            }
            #pragma unroll
            for (int in = 0; in < 4; in++) {
                int col = cbase + in * 8;
                float v0 = acc[im][in][half * 2 + 0] + bias[col];
                float v1 = acc[im][in][half * 2 + 1] + bias[col + 1];
                if (op == 1) {
                    v0 = 0.5f * v0 * (1.0f + erff(v0 * 0.70710678118654752f));
                    v1 = 0.5f * v1 * (1.0f + erff(v1 * 0.70710678118654752f));
                    v0 = to_tf32(v0); v1 = to_tf32(v1);
                }
                if (zero) { v0 = 0.f; v1 = 0.f; }
                float2 o; o.x = v0; o.y = v1;
                *(float2*)(C + (size_t)row * N + col) = o;
            }
        }
    }
}

// ------------------- tensor-core flash attention ---------------------------
// Block: 64 q rows, 4 warps (warp = m16 x n64). K-tiles of 64.
// QK^T: 2-pass split-Q tf32 (Q=big+small vs tf32 K). PV: 1x tf32, fp32 accum.
#define ATLD 68
#define ATTN_SMEM (5 * 64 * ATLD * 4)   // sQb sQs sK sV sP = 87040 B

__global__ __launch_bounds__(128)
void attn_tc_kernel(const float* __restrict__ QKV, float* __restrict__ O,
                    const int* __restrict__ start_pos)
{
    extern __shared__ float sm[];
    float* sQb = sm;
    float* sQs = sQb + 64 * ATLD;
    float* sK  = sQs + 64 * ATLD;
    float* sV  = sK  + 64 * ATLD;
    float* sP  = sV  + 64 * ATLD;

    int tid = threadIdx.x, lane = tid & 31, warp = tid >> 5;
    int qt = blockIdx.x, bh = blockIdx.y;
    int b = bh >> 4, h = bh & 15;
    int sp = start_pos[b];
    float slope = exp2f(-0.5f * (float)(h + 1));
    int brow = b * Sz;

    const float* Qg = QKV + h * 64;
    const float* Kg = QKV + 1024 + h * 64;
    const float* Vg = QKV + 2048 + h * 64;

    // load + scale + split Q tile (64 x 64)
    for (int i = tid; i < 64 * 16; i += 128) {
        int row = i >> 4, d4 = (i & 15) * 4;
        float4 v = *(const float4*)(Qg + (size_t)(brow + qt * 64 + row) * QKVN + d4);
        float s0 = v.x * 0.125f, s1 = v.y * 0.125f, s2 = v.z * 0.125f, s3 = v.w * 0.125f;
        float b0 = to_tf32(s0), b1 = to_tf32(s1), b2 = to_tf32(s2), b3 = to_tf32(s3);
        int o = row * ATLD + d4;
        sQb[o + 0] = b0; sQb[o + 1] = b1; sQb[o + 2] = b2; sQb[o + 3] = b3;
        sQs[o + 0] = to_tf32(s0 - b0); sQs[o + 1] = to_tf32(s1 - b1);
        sQs[o + 2] = to_tf32(s2 - b2); sQs[o + 3] = to_tf32(s3 - b3);
    }

    int qrow = warp * 16 + (lane >> 2);     // row of c0/c1 within 64-row tile
    int cA   = lane & 3;
    int ig0 = qt * 64 + qrow, ig1 = ig0 + 8;

    float m0 = -1e30f, m1 = -1e30f, l0 = 0.f, l1 = 0.f;
    float oacc[8][4];
    #pragma unroll
    for (int n = 0; n < 8; n++)
        #pragma unroll
        for (int r = 0; r < 4; r++) oacc[n][r] = 0.f;

    int ktmax = (qt * 64 >= sp) ? qt : 15;

    for (int kt = 0; kt <= ktmax; ++kt) {
        __syncthreads();
        for (int i = tid; i < 64 * 16; i += 128) {
            int row = i >> 4, d4 = (i & 15) * 4;
            float4 kv = *(const float4*)(Kg + (size_t)(brow + kt * 64 + row) * QKVN + d4);
            float4 vv = *(const float4*)(Vg + (size_t)(brow + kt * 64 + row) * QKVN + d4);
            int o = row * ATLD + d4;
            sK[o + 0] = to_tf32(kv.x); sK[o + 1] = to_tf32(kv.y);
            sK[o + 2] = to_tf32(kv.z); sK[o + 3] = to_tf32(kv.w);
            sV[o + 0] = to_tf32(vv.x); sV[o + 1] = to_tf32(vv.y);
            sV[o + 2] = to_tf32(vv.z); sV[o + 3] = to_tf32(vv.w);
        }
        __syncthreads();

        // ---- scores = Qb@K^T + Qs@K^T ----
        float sacc[8][4];
        #pragma unroll
        for (int n = 0; n < 8; n++)
            #pragma unroll
            for (int r = 0; r < 4; r++) sacc[n][r] = 0.f;

        #pragma unroll
        for (int ks = 0; ks < 8; ++ks) {
            uint32_t ab[4], as_[4];
            ab[0] = __float_as_uint(sQb[(qrow)     * ATLD + ks * 8 + cA]);
            ab[1] = __float_as_uint(sQb[(qrow + 8) * ATLD + ks * 8 + cA]);
            ab[2] = __float_as_uint(sQb[(qrow)     * ATLD + ks * 8 + 4 + cA]);
            ab[3] = __float_as_uint(sQb[(qrow + 8) * ATLD + ks * 8 + 4 + cA]);
            as_[0] = __float_as_uint(sQs[(qrow)     * ATLD + ks * 8 + cA]);
            as_[1] = __float_as_uint(sQs[(qrow + 8) * ATLD + ks * 8 + cA]);
            as_[2] = __float_as_uint(sQs[(qrow)     * ATLD + ks * 8 + 4 + cA]);
            as_[3] = __float_as_uint(sQs[(qrow + 8) * ATLD + ks * 8 + 4 + cA]);
            #pragma unroll
            for (int n = 0; n < 8; n++) {
                uint32_t bf[2];
                bf[0] = __float_as_uint(sK[(n * 8 + (lane >> 2)) * ATLD + ks * 8 + cA]);
                bf[1] = __float_as_uint(sK[(n * 8 + (lane >> 2)) * ATLD + ks * 8 + 4 + cA]);
                mma8(sacc[n], ab, bf);
                mma8(sacc[n], as_, bf);
            }
        }

        // ---- alibi + mask ----
        #pragma unroll
        for (int n = 0; n < 8; n++) {
            int jg = kt * 64 + n * 8 + cA * 2;
            #pragma unroll
            for (int half = 0; half < 2; half++) {
                int j = jg + half;
                float al = slope * (float)(j - sp);
                bool ok0 = (j <= ig0) || (ig0 < sp) || (j < sp);
                bool ok1 = (j <= ig1) || (ig1 < sp) || (j < sp);
                sacc[n][half]     = ok0 ? sacc[n][half]     + al : -1e30f;
                sacc[n][half + 2] = ok1 ? sacc[n][half + 2] + al : -1e30f;
            }
        }

        // ---- row max (quad reduction) ----
        float t0 = -1e30f, t1 = -1e30f;
        #pragma unroll
        for (int n = 0; n < 8; n++) {
            t0 = fmaxf(t0, fmaxf(sacc[n][0], sacc[n][1]));
            t1 = fmaxf(t1, fmaxf(sacc[n][2], sacc[n][3]));
        }
        t0 = fmaxf(t0, __shfl_xor_sync(0xffffffffu, t0, 1));
        t0 = fmaxf(t0, __shfl_xor_sync(0xffffffffu, t0, 2));
        t1 = fmaxf(t1, __shfl_xor_sync(0xffffffffu, t1, 1));
        t1 = fmaxf(t1, __shfl_xor_sync(0xffffffffu, t1, 2));

        float mn0 = fmaxf(m0, t0), mn1 = fmaxf(m1, t1);
        float scl0 = __expf(m0 - mn0), scl1 = __expf(m1 - mn1);
        m0 = mn0; m1 = mn1;

        // ---- exp, P store (tf32), partial l ----
        float ls0 = 0.f, ls1 = 0.f;
        #pragma unroll
        for (int n = 0; n < 8; n++) {
            int col = n * 8 + cA * 2;
            float p0 = to_tf32(__expf(sacc[n][0] - mn0));
            float p1 = to_tf32(__expf(sacc[n][1] - mn0));
            float p2 = to_tf32(__expf(sacc[n][2] - mn1));
            float p3 = to_tf32(__expf(sacc[n][3] - mn1));
            ls0 += p0 + p1;
            ls1 += p2 + p3;
            float2 w0; w0.x = p0; w0.y = p1;
            float2 w1; w1.x = p2; w1.y = p3;
            *(float2*)&sP[(qrow)     * ATLD + col] = w0;
            *(float2*)&sP[(qrow + 8) * ATLD + col] = w1;
        }
        ls0 += __shfl_xor_sync(0xffffffffu, ls0, 1);
        ls0 += __shfl_xor_sync(0xffffffffu, ls0, 2);
        ls1 += __shfl_xor_sync(0xffffffffu, ls1, 1);
        ls1 += __shfl_xor_sync(0xffffffffu, ls1, 2);
        l0 = l0 * scl0 + ls0;
        l1 = l1 * scl1 + ls1;

        #pragma unroll
        for (int n = 0; n < 8; n++) {
            oacc[n][0] *= scl0; oacc[n][1] *= scl0;
            oacc[n][2] *= scl1; oacc[n][3] *= scl1;
        }
        __syncwarp();

        // ---- O += P @ V ----
        #pragma unroll
        for (int ks = 0; ks < 8; ++ks) {
            uint32_t af[4];
            af[0] = __float_as_uint(sP[(qrow)     * ATLD + ks * 8 + cA]);
            af[1] = __float_as_uint(sP[(qrow + 8) * ATLD + ks * 8 + cA]);
            af[2] = __float_as_uint(sP[(qrow)     * ATLD + ks * 8 + 4 + cA]);
            af[3] = __float_as_uint(sP[(qrow + 8) * ATLD + ks * 8 + 4 + cA]);
            #pragma unroll
            for (int n = 0; n < 8; n++) {
                uint32_t bf[2];
                bf[0] = __float_as_uint(sV[(ks * 8 + cA)     * ATLD + n * 8 + (lane >> 2)]);
                bf[1] = __float_as_uint(sV[(ks * 8 + 4 + cA) * ATLD + n * 8 + (lane >> 2)]);
                mma8(oacc[n], af, bf);
            }
        }
        __syncwarp();
    }

    // ---- write out (tf32-rounded) ----
    float inv0 = 1.f / l0, inv1 = 1.f / l1;
    size_t orow0 = (size_t)(brow + qt * 64 + qrow) * Hz + h * 64;
    size_t orow1 = orow0 + (size_t)8 * Hz;
    #pragma unroll
    for (int n = 0; n < 8; n++) {
        int col = n * 8 + cA * 2;
        float2 w0, w1;
        w0.x = to_tf32(oacc[n][0] * inv0); w0.y = to_tf32(oacc[n][1] * inv0);
        w1.x = to_tf32(oacc[n][2] * inv1); w1.y = to_tf32(oacc[n][3] * inv1);
        *(float2*)(O + orow0 + col) = w0;
        *(float2*)(O + orow1 + col) = w1;
    }
}

// ------------------------ fused residual + layernorm -----------------------
__inline__ __device__ float warp_sum(float v) {
    #pragma unroll
    for (int o = 16; o; o >>= 1) v += __shfl_xor_sync(0xffffffffu, v, o);
    return v;
}

__global__ void add_ln_kernel(float* __restrict__ x, float* __restrict__ xc,
                              const float* __restrict__ t,
                              const float* __restrict__ g, const float* __restrict__ b)
{
    int row = blockIdx.x;
    int tid = threadIdx.x;
    size_t off = (size_t)row * Hz + tid * 4;

    float4 xv = *(const float4*)(x + off);
    float4 tv = *(const float4*)(t + off);
    float v0 = xv.x + tv.x, v1 = xv.y + tv.y, v2 = xv.z + tv.z, v3 = xv.w + tv.w;

    float s  = v0 + v1 + v2 + v3;
    float s2 = v0 * v0 + v1 * v1 + v2 * v2 + v3 * v3;

    __shared__ float sh1[8], sh2[8];
    int lane = tid & 31, wid = tid >> 5;
    s  = warp_sum(s);
    s2 = warp_sum(s2);
    if (lane == 0) { sh1[wid] = s; sh2[wid] = s2; }
    __syncthreads();
    if (wid == 0) {
        float a = (lane < 8) ? sh1[lane] : 0.f;
        float c = (lane < 8) ? sh2[lane] : 0.f;
        a = warp_sum(a);
        c = warp_sum(c);
        if (lane == 0) { sh1[0] = a; sh2[0] = c; }
    }
    __syncthreads();

    float mu  = sh1[0] * (1.0f / Hz);
    float var = sh2[0] * (1.0f / Hz) - mu * mu;
    float inv = rsqrtf(var + 1e-5f);

    int cbase = tid * 4;
    float4 gv = *(const float4*)(g + cbase);
    float4 bv = *(const float4*)(b + cbase);
    float4 out;
    out.x = (v0 - mu) * inv * gv.x + bv.x;
    out.y = (v1 - mu) * inv * gv.y + bv.y;
    out.z = (v2 - mu) * inv * gv.z + bv.z;
    out.w = (v3 - mu) * inv * gv.w + bv.w;
    *(float4*)(x + off) = out;
    float4 oc;
    oc.x = to_tf32(out.x); oc.y = to_tf32(out.y);
    oc.z = to_tf32(out.z); oc.w = to_tf32(out.w);
    *(float4*)(xc + off) = oc;
}

// --------------------------------- launch ----------------------------------
extern "C" void kernel_launch(void* const* d_in, const int* in_sizes, int n_in,
                              void* d_out, int out_size)
{
    const int*   ids  = (const int*)d_in[0];
    const int*   sp   = (const int*)d_in[1];
    const float* emb  = (const float*)d_in[2];
    const float* Wq   = (const float*)d_in[3];
    const float* bq   = (const float*)d_in[4];
    const float* Wk   = (const float*)d_in[5];
    const float* bk   = (const float*)d_in[6];
    const float* Wv   = (const float*)d_in[7];
    const float* bv   = (const float*)d_in[8];
    const float* Wo   = (const float*)d_in[9];
    const float* bo   = (const float*)d_in[10];
    const float* ln1g = (const float*)d_in[11];
    const float* ln1b = (const float*)d_in[12];
    const float* ln2g = (const float*)d_in[13];
    const float* ln2b = (const float*)d_in[14];
    const float* W1   = (const float*)d_in[15];
    const float* b1   = (const float*)d_in[16];
    const float* W2   = (const float*)d_in[17];
    const float* b2   = (const float*)d_in[18];
    const float* Wf   = (const float*)d_in[19];
    const float* bf   = (const float*)d_in[20];
    float* out = (float*)d_out;

    float *x, *xc, *qkv, *attnc, *tmp, *ffc, *w, *bqkv;
    cudaGetSymbolAddress((void**)&x,     g_x);
    cudaGetSymbolAddress((void**)&xc,    g_xc);
    cudaGetSymbolAddress((void**)&qkv,   g_qkv);
    cudaGetSymbolAddress((void**)&attnc, g_attnc);
    cudaGetSymbolAddress((void**)&tmp,   g_tmp);
    cudaGetSymbolAddress((void**)&ffc,   g_ffc);
    cudaGetSymbolAddress((void**)&w,     g_w);
    cudaGetSymbolAddress((void**)&bqkv,  g_bqkv);

    cudaFuncSetAttribute(attn_tc_kernel, cudaFuncAttributeMaxDynamicSharedMemorySize, ATTN_SMEM);
    cudaFuncSetAttribute(gemm_tc_kernel, cudaFuncAttributeMaxDynamicSharedMemorySize, GEMM_SMEM);

    cvt_qkv_kernel<<<(Lz * Hz * QKVN) / 256, 256>>>(Wq, Wk, Wv, w + OFF_QKV);
    cvt_bias_kernel<<<(Lz * QKVN) / 256, 256>>>(bq, bk, bv, bqkv);
    cvt4_kernel<<<(Lz * Hz * Hz / 4) / 256, 256>>>(Wo, w + OFF_WO, Lz * Hz * Hz / 4);
    cvt4_kernel<<<(Lz * Hz * DFz / 4) / 256, 256>>>(W1, w + OFF_W1, Lz * Hz * DFz / 4);
    cvt4_kernel<<<(Lz * DFz * Hz / 4) / 256, 256>>>(W2, w + OFF_W2, Lz * DFz * Hz / 4);
    cvt4_kernel<<<(Hz * Vz / 4) / 256, 256>>>(Wf, w + OFF_WF, Hz * Vz / 4);

    embed_kernel<<<Mz, 256>>>(ids, emb, x, xc);

    for (int l = 0; l < Lz; ++l) {
        gemm_tc_kernel<<<dim3(QKVN / 128, Mz / 128), 256, GEMM_SMEM>>>(
            xc, w + OFF_QKV + (size_t)l * Hz * QKVN, bqkv + l * QKVN, qkv,
            Mz, QKVN, Hz, 0, sp);

        attn_tc_kernel<<<dim3(Sz / 64, Bz * NHz), 128, ATTN_SMEM>>>(qkv, attnc, sp);

        gemm_tc_kernel<<<dim3(Hz / 128, Mz / 128), 256, GEMM_SMEM>>>(
            attnc, w + OFF_WO + (size_t)l * Hz * Hz, bo + l * Hz, tmp,
            Mz, Hz, Hz, 0, sp);
        add_ln_kernel<<<Mz, 256>>>(x, xc, tmp, ln1g + l * Hz, ln1b + l * Hz);

        gemm_tc_kernel<<<dim3(DFz / 128, Mz / 128), 256, GEMM_SMEM>>>(
            xc, w + OFF_W1 + (size_t)l * Hz * DFz, b1 + l * DFz, ffc,
            Mz, DFz, Hz, 1, sp);
        gemm_tc_kernel<<<dim3(Hz / 128, Mz / 128), 256, GEMM_SMEM>>>(
            ffc, w + OFF_W2 + (size_t)l * DFz * Hz, b2 + l * Hz, tmp,
            Mz, Hz, DFz, 0, sp);
        add_ln_kernel<<<Mz, 256>>>(x, xc, tmp, ln2g + l * Hz, ln2b + l * Hz);
    }

    gemm_tc_kernel<<<dim3(Vz / 128, Mz / 128), 256, GEMM_SMEM>>>(
        xc, w + OFF_WF, bf, out, Mz, Vz, Hz, 2, sp);
}

// round 6
// speedup vs baseline: 4.1418x; 1.0071x over previous
#include <cuda_runtime.h>
#include <cuda_bf16.h>
#include <math.h>
#include <stdint.h>

// ---------------------------------------------------------------------------
// TidalTransformer: B=4, S=1024, H=1024, NH=16, DK=64, DF=4096, L=4, V=32000
// Round 6: legacy-mma tf32 GEMM with 128x256 CTA tile / 64x64 warp tile
//          (tcgen05 unavailable: harness PTX targets sm_103, not sm_103a),
//          TC flash attention, fused LN.
// ---------------------------------------------------------------------------

#define Bz   4
#define Sz   1024
#define Hz   1024
#define NHz  16
#define DKz  64
#define DFz  4096
#define Lz   4
#define Vz   32000
#define Mz   (Bz * Sz)
#define QKVN 3072

// ------------------------- scratch (device globals) ------------------------
__device__ float g_x   [(size_t)Mz * Hz];
__device__ float g_xc  [(size_t)Mz * Hz];
__device__ float g_qkv [(size_t)Mz * QKVN];
__device__ float g_attnc[(size_t)Mz * Hz];
__device__ float g_tmp [(size_t)Mz * Hz];
__device__ float g_ffc [(size_t)Mz * DFz];

#define OFF_QKV 0
#define OFF_WO  ((size_t)12582912)
#define OFF_W1  ((size_t)16777216)
#define OFF_W2  ((size_t)33554432)
#define OFF_WF  ((size_t)50331648)
__device__ float g_w[(size_t)83099648];
__device__ float g_bqkv[Lz * QKVN];

__device__ __forceinline__ float to_tf32(float x) {
    float r;
    asm("cvt.rna.tf32.f32 %0, %1;" : "=f"(r) : "f"(x));
    return r;
}

// ----------------------------- converters ----------------------------------
__global__ void cvt4_kernel(const float* __restrict__ s, float* __restrict__ d, int n4)
{
    int i = blockIdx.x * 256 + threadIdx.x;
    if (i < n4) {
        float4 v = ((const float4*)s)[i];
        v.x = to_tf32(v.x); v.y = to_tf32(v.y); v.z = to_tf32(v.z); v.w = to_tf32(v.w);
        ((float4*)d)[i] = v;
    }
}

__global__ void cvt_qkv_kernel(const float* __restrict__ Wq, const float* __restrict__ Wk,
                               const float* __restrict__ Wv, float* __restrict__ dst)
{
    size_t i = (size_t)blockIdx.x * 256 + threadIdx.x;
    int n = (int)(i % QKVN);
    size_t lk = i / QKVN;
    float v;
    if (n < 1024)       v = Wq[lk * 1024 + n];
    else if (n < 2048)  v = Wk[lk * 1024 + n - 1024];
    else                v = Wv[lk * 1024 + n - 2048];
    dst[i] = to_tf32(v);
}

__global__ void cvt_bias_kernel(const float* __restrict__ bq, const float* __restrict__ bk,
                                const float* __restrict__ bv, float* __restrict__ dst)
{
    int i = blockIdx.x * 256 + threadIdx.x;
    int n = i % QKVN, l = i / QKVN;
    float v;
    if (n < 1024)       v = bq[l * 1024 + n];
    else if (n < 2048)  v = bk[l * 1024 + n - 1024];
    else                v = bv[l * 1024 + n - 2048];
    dst[i] = v;
}

// ------------------------------- embedding ---------------------------------
__global__ void embed_kernel(const int* __restrict__ ids,
                             const float* __restrict__ emb,
                             float* __restrict__ x, float* __restrict__ xc)
{
    int row = blockIdx.x;
    int tid = threadIdx.x;
    int id  = ids[row];
    float4 v = *(const float4*)(emb + (size_t)id * Hz + tid * 4);
    v.x *= 32.0f; v.y *= 32.0f; v.z *= 32.0f; v.w *= 32.0f;
    *(float4*)(x + (size_t)row * Hz + tid * 4) = v;
    float4 c;
    c.x = to_tf32(v.x); c.y = to_tf32(v.y); c.z = to_tf32(v.z); c.w = to_tf32(v.w);
    *(float4*)(xc + (size_t)row * Hz + tid * 4) = c;
}

// ---------------- tf32 GEMM: 128x256 tile, warp 64x64, cp.async ------------
#define ASTR 36
#define BSTR 264
#define AS_STAGE (128 * ASTR)   // 4608 floats
#define BS_STAGE (32 * BSTR)    // 8448 floats
#define GEMM_SMEM (3 * (AS_STAGE + BS_STAGE) * 4)   // 156672 bytes

__device__ __forceinline__ void cpasync16(uint32_t dst, const void* src) {
    asm volatile("cp.async.cg.shared.global [%0], [%1], 16;" :: "r"(dst), "l"(src));
}

__device__ __forceinline__ void mma8(float* c, const uint32_t* a, const uint32_t* b) {
    asm volatile(
        "mma.sync.aligned.m16n8k8.row.col.f32.tf32.tf32.f32 "
        "{%0,%1,%2,%3},{%4,%5,%6,%7},{%8,%9},{%0,%1,%2,%3};"
        : "+f"(c[0]), "+f"(c[1]), "+f"(c[2]), "+f"(c[3])
        : "r"(a[0]), "r"(a[1]), "r"(a[2]), "r"(a[3]), "r"(b[0]), "r"(b[1]));
}

__global__ __launch_bounds__(256, 1)
void gemm_tc_kernel(const float* __restrict__ A, const float* __restrict__ W,
                    const float* __restrict__ bias, float* __restrict__ C,
                    int M, int N, int K, int op, const int* __restrict__ start_pos)
{
    extern __shared__ float sm_[];
    float* As = sm_;                    // [3][128][36]
    float* Bs = sm_ + 3 * AS_STAGE;     // [3][32][264]

    int tid = threadIdx.x, lane = tid & 31, warp = tid >> 5;
    int wm = warp & 1, wn = warp >> 1;          // 2m x 4n, warp tile 64x64
    int m0 = blockIdx.y * 128, n0 = blockIdx.x * 256;

    // copy geometry
    int arow = tid >> 3;            // 0..31 (+i*32)
    int ac4  = (tid & 7) * 4;       // 0..28
    int bk_  = tid >> 6;            // 0..3  (+i*4)
    int bn4  = (tid & 63) * 4;      // 0..252

    const float* aBase = A + (size_t)(m0 + arow) * K + ac4;
    const float* wBase = W + (size_t)bk_ * N + n0 + bn4;

    uint32_t asBase = (uint32_t)__cvta_generic_to_shared(As);
    uint32_t bsBase = (uint32_t)__cvta_generic_to_shared(Bs);
    uint32_t asOff = (uint32_t)(arow * ASTR + ac4) * 4;
    uint32_t bsOff = (uint32_t)(bk_ * BSTR + bn4) * 4;

    float acc[4][8][4];
    #pragma unroll
    for (int i = 0; i < 4; i++)
        #pragma unroll
        for (int j = 0; j < 8; j++)
            #pragma unroll
            for (int r = 0; r < 4; r++) acc[i][j][r] = 0.f;

    int KT = K >> 5;

    // prologue: stages 0,1
    #pragma unroll
    for (int s = 0; s < 2; s++) {
        int kk = s * 32;
        #pragma unroll
        for (int i = 0; i < 4; i++)
            cpasync16(asBase + s * (AS_STAGE * 4) + asOff + i * (32 * ASTR * 4),
                      aBase + (size_t)i * 32 * K + kk);
        #pragma unroll
        for (int i = 0; i < 8; i++)
            cpasync16(bsBase + s * (BS_STAGE * 4) + bsOff + i * (4 * BSTR * 4),
                      wBase + (size_t)(kk + i * 4) * N);
        asm volatile("cp.async.commit_group;");
    }

    int aoff = (wm * 64 + (lane >> 2)) * ASTR + (lane & 3);
    int boff = (lane & 3) * BSTR + wn * 64 + (lane >> 2);

    for (int kt = 0; kt < KT; ++kt) {
        asm volatile("cp.async.wait_group 1;" ::: "memory");
        __syncthreads();

        if (kt + 2 < KT) {
            int s = (kt + 2) % 3;
            int kk = (kt + 2) * 32;
            #pragma unroll
            for (int i = 0; i < 4; i++)
                cpasync16(asBase + s * (AS_STAGE * 4) + asOff + i * (32 * ASTR * 4),
                          aBase + (size_t)i * 32 * K + kk);
            #pragma unroll
            for (int i = 0; i < 8; i++)
                cpasync16(bsBase + s * (BS_STAGE * 4) + bsOff + i * (4 * BSTR * 4),
                          wBase + (size_t)(kk + i * 4) * N);
        }
        asm volatile("cp.async.commit_group;");

        const float* aP = As + (kt % 3) * AS_STAGE + aoff;
        const float* bP = Bs + (kt % 3) * BS_STAGE + boff;

        #pragma unroll
        for (int ks = 0; ks < 4; ++ks) {
            uint32_t af[4][4], bfr[8][2];
            #pragma unroll
            for (int im = 0; im < 4; im++) {
                af[im][0] = __float_as_uint(aP[(im * 16)     * ASTR + ks * 8]);
                af[im][1] = __float_as_uint(aP[(im * 16 + 8) * ASTR + ks * 8]);
                af[im][2] = __float_as_uint(aP[(im * 16)     * ASTR + ks * 8 + 4]);
                af[im][3] = __float_as_uint(aP[(im * 16 + 8) * ASTR + ks * 8 + 4]);
            }
            #pragma unroll
            for (int in = 0; in < 8; in++) {
                bfr[in][0] = __float_as_uint(bP[(ks * 8)     * BSTR + in * 8]);
                bfr[in][1] = __float_as_uint(bP[(ks * 8 + 4) * BSTR + in * 8]);
            }
            #pragma unroll
            for (int im = 0; im < 4; im++)
                #pragma unroll
                for (int in = 0; in < 8; in++)
                    mma8(acc[im][in], af[im], bfr[in]);
        }
    }

    // epilogue
    int rbase = m0 + wm * 64 + (lane >> 2);
    int cbase = n0 + wn * 64 + ((lane & 3) << 1);
    #pragma unroll
    for (int im = 0; im < 4; im++) {
        #pragma unroll
        for (int half = 0; half < 2; half++) {
            int row = rbase + im * 16 + half * 8;
            bool zero = false;
            if (op == 2) {
                int b = row >> 10;
                zero = (row & 1023) < start_pos[b];
            }
            #pragma unroll
            for (int in = 0; in < 8; in++) {
                int col = cbase + in * 8;
                float v0 = acc[im][in][half * 2 + 0] + bias[col];
                float v1 = acc[im][in][half * 2 + 1] + bias[col + 1];
                if (op == 1) {
                    v0 = 0.5f * v0 * (1.0f + erff(v0 * 0.70710678118654752f));
                    v1 = 0.5f * v1 * (1.0f + erff(v1 * 0.70710678118654752f));
                    v0 = to_tf32(v0); v1 = to_tf32(v1);
                }
                if (zero) { v0 = 0.f; v1 = 0.f; }
                float2 o; o.x = v0; o.y = v1;
                *(float2*)(C + (size_t)row * N + col) = o;
            }
        }
    }
}

// ------------------- tensor-core flash attention ---------------------------
#define ATLD 68
#define ATTN_SMEM (5 * 64 * ATLD * 4)

__global__ __launch_bounds__(128)
void attn_tc_kernel(const float* __restrict__ QKV, float* __restrict__ O,
                    const int* __restrict__ start_pos)
{
    extern __shared__ float sm[];
    float* sQb = sm;
    float* sQs = sQb + 64 * ATLD;
    float* sK  = sQs + 64 * ATLD;
    float* sV  = sK  + 64 * ATLD;
    float* sP  = sV  + 64 * ATLD;

    int tid = threadIdx.x, lane = tid & 31, warp = tid >> 5;
    int qt = blockIdx.x, bh = blockIdx.y;
    int b = bh >> 4, h = bh & 15;
    int sp = start_pos[b];
    float slope = exp2f(-0.5f * (float)(h + 1));
    int brow = b * Sz;

    const float* Qg = QKV + h * 64;
    const float* Kg = QKV + 1024 + h * 64;
    const float* Vg = QKV + 2048 + h * 64;

    for (int i = tid; i < 64 * 16; i += 128) {
        int row = i >> 4, d4 = (i & 15) * 4;
        float4 v = *(const float4*)(Qg + (size_t)(brow + qt * 64 + row) * QKVN + d4);
        float s0 = v.x * 0.125f, s1 = v.y * 0.125f, s2 = v.z * 0.125f, s3 = v.w * 0.125f;
        float b0 = to_tf32(s0), b1 = to_tf32(s1), b2 = to_tf32(s2), b3 = to_tf32(s3);
        int o = row * ATLD + d4;
        sQb[o + 0] = b0; sQb[o + 1] = b1; sQb[o + 2] = b2; sQb[o + 3] = b3;
        sQs[o + 0] = to_tf32(s0 - b0); sQs[o + 1] = to_tf32(s1 - b1);
        sQs[o + 2] = to_tf32(s2 - b2); sQs[o + 3] = to_tf32(s3 - b3);
    }

    int qrow = warp * 16 + (lane >> 2);
    int cA   = lane & 3;
    int ig0 = qt * 64 + qrow, ig1 = ig0 + 8;

    float m0 = -1e30f, m1 = -1e30f, l0 = 0.f, l1 = 0.f;
    float oacc[8][4];
    #pragma unroll
    for (int n = 0; n < 8; n++)
        #pragma unroll
        for (int r = 0; r < 4; r++) oacc[n][r] = 0.f;

    int ktmax = (qt * 64 >= sp) ? qt : 15;

    for (int kt = 0; kt <= ktmax; ++kt) {
        __syncthreads();
        for (int i = tid; i < 64 * 16; i += 128) {
            int row = i >> 4, d4 = (i & 15) * 4;
            float4 kv = *(const float4*)(Kg + (size_t)(brow + kt * 64 + row) * QKVN + d4);
            float4 vv = *(const float4*)(Vg + (size_t)(brow + kt * 64 + row) * QKVN + d4);
            int o = row * ATLD + d4;
            sK[o + 0] = to_tf32(kv.x); sK[o + 1] = to_tf32(kv.y);
            sK[o + 2] = to_tf32(kv.z); sK[o + 3] = to_tf32(kv.w);
            sV[o + 0] = to_tf32(vv.x); sV[o + 1] = to_tf32(vv.y);
            sV[o + 2] = to_tf32(vv.z); sV[o + 3] = to_tf32(vv.w);
        }
        __syncthreads();

        float sacc[8][4];
        #pragma unroll
        for (int n = 0; n < 8; n++)
            #pragma unroll
            for (int r = 0; r < 4; r++) sacc[n][r] = 0.f;

        #pragma unroll
        for (int ks = 0; ks < 8; ++ks) {
            uint32_t ab[4], as_[4];
            ab[0] = __float_as_uint(sQb[(qrow)     * ATLD + ks * 8 + cA]);
            ab[1] = __float_as_uint(sQb[(qrow + 8) * ATLD + ks * 8 + cA]);
            ab[2] = __float_as_uint(sQb[(qrow)     * ATLD + ks * 8 + 4 + cA]);
            ab[3] = __float_as_uint(sQb[(qrow + 8) * ATLD + ks * 8 + 4 + cA]);
            as_[0] = __float_as_uint(sQs[(qrow)     * ATLD + ks * 8 + cA]);
            as_[1] = __float_as_uint(sQs[(qrow + 8) * ATLD + ks * 8 + cA]);
            as_[2] = __float_as_uint(sQs[(qrow)     * ATLD + ks * 8 + 4 + cA]);
            as_[3] = __float_as_uint(sQs[(qrow + 8) * ATLD + ks * 8 + 4 + cA]);
            #pragma unroll
            for (int n = 0; n < 8; n++) {
                uint32_t bf[2];
                bf[0] = __float_as_uint(sK[(n * 8 + (lane >> 2)) * ATLD + ks * 8 + cA]);
                bf[1] = __float_as_uint(sK[(n * 8 + (lane >> 2)) * ATLD + ks * 8 + 4 + cA]);
                mma8(sacc[n], ab, bf);
                mma8(sacc[n], as_, bf);
            }
        }

        #pragma unroll
        for (int n = 0; n < 8; n++) {
            int jg = kt * 64 + n * 8 + cA * 2;
            #pragma unroll
            for (int half = 0; half < 2; half++) {
                int j = jg + half;
                float al = slope * (float)(j - sp);
                bool ok0 = (j <= ig0) || (ig0 < sp) || (j < sp);
                bool ok1 = (j <= ig1) || (ig1 < sp) || (j < sp);
                sacc[n][half]     = ok0 ? sacc[n][half]     + al : -1e30f;
                sacc[n][half + 2] = ok1 ? sacc[n][half + 2] + al : -1e30f;
            }
        }

        float t0 = -1e30f, t1 = -1e30f;
        #pragma unroll
        for (int n = 0; n < 8; n++) {
            t0 = fmaxf(t0, fmaxf(sacc[n][0], sacc[n][1]));
            t1 = fmaxf(t1, fmaxf(sacc[n][2], sacc[n][3]));
        }
        t0 = fmaxf(t0, __shfl_xor_sync(0xffffffffu, t0, 1));
        t0 = fmaxf(t0, __shfl_xor_sync(0xffffffffu, t0, 2));
        t1 = fmaxf(t1, __shfl_xor_sync(0xffffffffu, t1, 1));
        t1 = fmaxf(t1, __shfl_xor_sync(0xffffffffu, t1, 2));

        float mn0 = fmaxf(m0, t0), mn1 = fmaxf(m1, t1);
        float scl0 = __expf(m0 - mn0), scl1 = __expf(m1 - mn1);
        m0 = mn0; m1 = mn1;

        float ls0 = 0.f, ls1 = 0.f;
        #pragma unroll
        for (int n = 0; n < 8; n++) {
            int col = n * 8 + cA * 2;
            float p0 = to_tf32(__expf(sacc[n][0] - mn0));
            float p1 = to_tf32(__expf(sacc[n][1] - mn0));
            float p2 = to_tf32(__expf(sacc[n][2] - mn1));
            float p3 = to_tf32(__expf(sacc[n][3] - mn1));
            ls0 += p0 + p1;
            ls1 += p2 + p3;
            float2 w0; w0.x = p0; w0.y = p1;
            float2 w1; w1.x = p2; w1.y = p3;
            *(float2*)&sP[(qrow)     * ATLD + col] = w0;
            *(float2*)&sP[(qrow + 8) * ATLD + col] = w1;
        }
        ls0 += __shfl_xor_sync(0xffffffffu, ls0, 1);
        ls0 += __shfl_xor_sync(0xffffffffu, ls0, 2);
        ls1 += __shfl_xor_sync(0xffffffffu, ls1, 1);
        ls1 += __shfl_xor_sync(0xffffffffu, ls1, 2);
        l0 = l0 * scl0 + ls0;
        l1 = l1 * scl1 + ls1;

        #pragma unroll
        for (int n = 0; n < 8; n++) {
            oacc[n][0] *= scl0; oacc[n][1] *= scl0;
            oacc[n][2] *= scl1; oacc[n][3] *= scl1;
        }
        __syncwarp();

        #pragma unroll
        for (int ks = 0; ks < 8; ++ks) {
            uint32_t af[4];
            af[0] = __float_as_uint(sP[(qrow)     * ATLD + ks * 8 + cA]);
            af[1] = __float_as_uint(sP[(qrow + 8) * ATLD + ks * 8 + cA]);
            af[2] = __float_as_uint(sP[(qrow)     * ATLD + ks * 8 + 4 + cA]);
            af[3] = __float_as_uint(sP[(qrow + 8) * ATLD + ks * 8 + 4 + cA]);
            #pragma unroll
            for (int n = 0; n < 8; n++) {
                uint32_t bf[2];
                bf[0] = __float_as_uint(sV[(ks * 8 + cA)     * ATLD + n * 8 + (lane >> 2)]);
                bf[1] = __float_as_uint(sV[(ks * 8 + 4 + cA) * ATLD + n * 8 + (lane >> 2)]);
                mma8(oacc[n], af, bf);
            }
        }
        __syncwarp();
    }

    float inv0 = 1.f / l0, inv1 = 1.f / l1;
    size_t orow0 = (size_t)(brow + qt * 64 + qrow) * Hz + h * 64;
    size_t orow1 = orow0 + (size_t)8 * Hz;
    #pragma unroll
    for (int n = 0; n < 8; n++) {
        int col = n * 8 + cA * 2;
        float2 w0, w1;
        w0.x = to_tf32(oacc[n][0] * inv0); w0.y = to_tf32(oacc[n][1] * inv0);
        w1.x = to_tf32(oacc[n][2] * inv1); w1.y = to_tf32(oacc[n][3] * inv1);
        *(float2*)(O + orow0 + col) = w0;
        *(float2*)(O + orow1 + col) = w1;
    }
}

// ------------------------ fused residual + layernorm -----------------------
__inline__ __device__ float warp_sum(float v) {
    #pragma unroll
    for (int o = 16; o; o >>= 1) v += __shfl_xor_sync(0xffffffffu, v, o);
    return v;
}

__global__ void add_ln_kernel(float* __restrict__ x, float* __restrict__ xc,
                              const float* __restrict__ t,
                              const float* __restrict__ g, const float* __restrict__ b)
{
    int row = blockIdx.x;
    int tid = threadIdx.x;
    size_t off = (size_t)row * Hz + tid * 4;

    float4 xv = *(const float4*)(x + off);
    float4 tv = *(const float4*)(t + off);
    float v0 = xv.x + tv.x, v1 = xv.y + tv.y, v2 = xv.z + tv.z, v3 = xv.w + tv.w;

    float s  = v0 + v1 + v2 + v3;
    float s2 = v0 * v0 + v1 * v1 + v2 * v2 + v3 * v3;

    __shared__ float sh1[8], sh2[8];
    int lane = tid & 31, wid = tid >> 5;
    s  = warp_sum(s);
    s2 = warp_sum(s2);
    if (lane == 0) { sh1[wid] = s; sh2[wid] = s2; }
    __syncthreads();
    if (wid == 0) {
        float a = (lane < 8) ? sh1[lane] : 0.f;
        float c = (lane < 8) ? sh2[lane] : 0.f;
        a = warp_sum(a);
        c = warp_sum(c);
        if (lane == 0) { sh1[0] = a; sh2[0] = c; }
    }
    __syncthreads();

    float mu  = sh1[0] * (1.0f / Hz);
    float var = sh2[0] * (1.0f / Hz) - mu * mu;
    float inv = rsqrtf(var + 1e-5f);

    int cbase = tid * 4;
    float4 gv = *(const float4*)(g + cbase);
    float4 bv = *(const float4*)(b + cbase);
    float4 out;
    out.x = (v0 - mu) * inv * gv.x + bv.x;
    out.y = (v1 - mu) * inv * gv.y + bv.y;
    out.z = (v2 - mu) * inv * gv.z + bv.z;
    out.w = (v3 - mu) * inv * gv.w + bv.w;
    *(float4*)(x + off) = out;
    float4 oc;
    oc.x = to_tf32(out.x); oc.y = to_tf32(out.y);
    oc.z = to_tf32(out.z); oc.w = to_tf32(out.w);
    *(float4*)(xc + off) = oc;
}

// --------------------------------- launch ----------------------------------
extern "C" void kernel_launch(void* const* d_in, const int* in_sizes, int n_in,
                              void* d_out, int out_size)
{
    const int*   ids  = (const int*)d_in[0];
    const int*   sp   = (const int*)d_in[1];
    const float* emb  = (const float*)d_in[2];
    const float* Wq   = (const float*)d_in[3];
    const float* bq   = (const float*)d_in[4];
    const float* Wk   = (const float*)d_in[5];
    const float* bk   = (const float*)d_in[6];
    const float* Wv   = (const float*)d_in[7];
    const float* bv   = (const float*)d_in[8];
    const float* Wo   = (const float*)d_in[9];
    const float* bo   = (const float*)d_in[10];
    const float* ln1g = (const float*)d_in[11];
    const float* ln1b = (const float*)d_in[12];
    const float* ln2g = (const float*)d_in[13];
    const float* ln2b = (const float*)d_in[14];
    const float* W1   = (const float*)d_in[15];
    const float* b1   = (const float*)d_in[16];
    const float* W2   = (const float*)d_in[17];
    const float* b2   = (const float*)d_in[18];
    const float* Wf   = (const float*)d_in[19];
    const float* bf   = (const float*)d_in[20];
    float* out = (float*)d_out;

    float *x, *xc, *qkv, *attnc, *tmp, *ffc, *w, *bqkv;
    cudaGetSymbolAddress((void**)&x,     g_x);
    cudaGetSymbolAddress((void**)&xc,    g_xc);
    cudaGetSymbolAddress((void**)&qkv,   g_qkv);
    cudaGetSymbolAddress((void**)&attnc, g_attnc);
    cudaGetSymbolAddress((void**)&tmp,   g_tmp);
    cudaGetSymbolAddress((void**)&ffc,   g_ffc);
    cudaGetSymbolAddress((void**)&w,     g_w);
    cudaGetSymbolAddress((void**)&bqkv,  g_bqkv);

    cudaFuncSetAttribute(attn_tc_kernel, cudaFuncAttributeMaxDynamicSharedMemorySize, ATTN_SMEM);
    cudaFuncSetAttribute(gemm_tc_kernel, cudaFuncAttributeMaxDynamicSharedMemorySize, GEMM_SMEM);

    cvt_qkv_kernel<<<(Lz * Hz * QKVN) / 256, 256>>>(Wq, Wk, Wv, w + OFF_QKV);
    cvt_bias_kernel<<<(Lz * QKVN) / 256, 256>>>(bq, bk, bv, bqkv);
    cvt4_kernel<<<(Lz * Hz * Hz / 4) / 256, 256>>>(Wo, w + OFF_WO, Lz * Hz * Hz / 4);
    cvt4_kernel<<<(Lz * Hz * DFz / 4) / 256, 256>>>(W1, w + OFF_W1, Lz * Hz * DFz / 4);
    cvt4_kernel<<<(Lz * DFz * Hz / 4) / 256, 256>>>(W2, w + OFF_W2, Lz * DFz * Hz / 4);
    cvt4_kernel<<<(Hz * Vz / 4) / 256, 256>>>(Wf, w + OFF_WF, Hz * Vz / 4);

    embed_kernel<<<Mz, 256>>>(ids, emb, x, xc);

    for (int l = 0; l < Lz; ++l) {
        gemm_tc_kernel<<<dim3(QKVN / 256, Mz / 128), 256, GEMM_SMEM>>>(
            xc, w + OFF_QKV + (size_t)l * Hz * QKVN, bqkv + l * QKVN, qkv,
            Mz, QKVN, Hz, 0, sp);

        attn_tc_kernel<<<dim3(Sz / 64, Bz * NHz), 128, ATTN_SMEM>>>(qkv, attnc, sp);

        gemm_tc_kernel<<<dim3(Hz / 256, Mz / 128), 256, GEMM_SMEM>>>(
            attnc, w + OFF_WO + (size_t)l * Hz * Hz, bo + l * Hz, tmp,
            Mz, Hz, Hz, 0, sp);
        add_ln_kernel<<<Mz, 256>>>(x, xc, tmp, ln1g + l * Hz, ln1b + l * Hz);

        gemm_tc_kernel<<<dim3(DFz / 256, Mz / 128), 256, GEMM_SMEM>>>(
            xc, w + OFF_W1 + (size_t)l * Hz * DFz, b1 + l * DFz, ffc,
            Mz, DFz, Hz, 1, sp);
        gemm_tc_kernel<<<dim3(Hz / 256, Mz / 128), 256, GEMM_SMEM>>>(
            ffc, w + OFF_W2 + (size_t)l * DFz * Hz, b2 + l * Hz, tmp,
            Mz, Hz, DFz, 0, sp);
        add_ln_kernel<<<Mz, 256>>>(x, xc, tmp, ln2g + l * Hz, ln2b + l * Hz);
    }

    gemm_tc_kernel<<<dim3(Vz / 256, Mz / 128), 256, GEMM_SMEM>>>(
        xc, w + OFF_WF, bf, out, Mz, Vz, Hz, 2, sp);
}

// round 7
// speedup vs baseline: 5.3025x; 1.2802x over previous
#include <cuda_runtime.h>
#include <cuda_fp16.h>
#include <math.h>
#include <stdint.h>

// ---------------------------------------------------------------------------
// TidalTransformer: B=4, S=1024, H=1024, NH=16, DK=64, DF=4096, L=4, V=32000
// Round 7: fp16-operand GEMMs (mma.m16n8k16.f16, fp32 accum), half activations,
//          single-pass tf32 flash attention (fp16 operands are tf32-exact),
//          fp32 residual stream, fused LN.
// ---------------------------------------------------------------------------

#define Bz   4
#define Sz   1024
#define Hz   1024
#define NHz  16
#define DKz  64
#define DFz  4096
#define Lz   4
#define Vz   32000
#define Mz   (Bz * Sz)
#define QKVN 3072

// ------------------------- scratch (device globals) ------------------------
__device__ float  g_x   [(size_t)Mz * Hz];      // fp32 residual stream
__device__ __half g_xch [(size_t)Mz * Hz];      // fp16 copy of x
__device__ __half g_qkv [(size_t)Mz * QKVN];    // fused q|k|v (fp16)
__device__ __half g_attnc[(size_t)Mz * Hz];     // attention out (fp16)
__device__ float  g_tmp [(size_t)Mz * Hz];      // gemm out (fp32, pre-LN)
__device__ __half g_ffc [(size_t)Mz * DFz];     // gelu out (fp16)

// fp16 TRANSPOSED weight pool: all stored [N, K], K contiguous
#define OFF_QKV 0
#define OFF_WO  ((size_t)12582912)
#define OFF_W1  ((size_t)16777216)
#define OFF_W2  ((size_t)33554432)
#define OFF_WF  ((size_t)50331648)
__device__ __half g_w[(size_t)83099648];
__device__ float  g_bqkv[Lz * QKVN];

__device__ __forceinline__ float to_tf32(float x) {
    float r;
    asm("cvt.rna.tf32.f32 %0, %1;" : "=f"(r) : "f"(x));
    return r;
}

// --------------------- transpose + fp16 convert ----------------------------
// src [K, N] fp32 row-major -> dst [N, K] fp16 row-major.
__global__ void transT_kernel(const float* __restrict__ src, __half* __restrict__ dst,
                              int K, int N)
{
    __shared__ float t[32][33];
    int kb = blockIdx.x * 32, nb = blockIdx.y * 32;
    int tx = threadIdx.x, ty = threadIdx.y;   // 32 x 8
    #pragma unroll
    for (int i = 0; i < 4; i++)
        t[ty + i * 8][tx] = src[(size_t)(kb + ty + i * 8) * N + nb + tx];
    __syncthreads();
    #pragma unroll
    for (int i = 0; i < 4; i++)
        dst[(size_t)(nb + ty + i * 8) * K + kb + tx] = __float2half_rn(t[tx][ty + i * 8]);
}

__global__ void cvt_bias_kernel(const float* __restrict__ bq, const float* __restrict__ bk,
                                const float* __restrict__ bv, float* __restrict__ dst)
{
    int i = blockIdx.x * 256 + threadIdx.x;
    int n = i % QKVN, l = i / QKVN;
    float v;
    if (n < 1024)       v = bq[l * 1024 + n];
    else if (n < 2048)  v = bk[l * 1024 + n - 1024];
    else                v = bv[l * 1024 + n - 2048];
    dst[i] = v;
}

// ------------------------------- embedding ---------------------------------
__global__ void embed_kernel(const int* __restrict__ ids,
                             const float* __restrict__ emb,
                             float* __restrict__ x, __half* __restrict__ xch)
{
    int row = blockIdx.x;
    int tid = threadIdx.x;
    int id  = ids[row];
    float4 v = *(const float4*)(emb + (size_t)id * Hz + tid * 4);
    v.x *= 32.0f; v.y *= 32.0f; v.z *= 32.0f; v.w *= 32.0f;
    *(float4*)(x + (size_t)row * Hz + tid * 4) = v;
    __half2 h0 = __floats2half2_rn(v.x, v.y);
    __half2 h1 = __floats2half2_rn(v.z, v.w);
    *(__half2*)(xch + (size_t)row * Hz + tid * 4)     = h0;
    *(__half2*)(xch + (size_t)row * Hz + tid * 4 + 2) = h1;
}

// ------------------ fp16 GEMM: 128x128 tile, BK=64, 3-stage ----------------
// C = A[M,K](fp16) @ Wt[N,K](fp16)^T + bias(fp32).
// op: 0=write half, 1=GELU->half, 2=rowmask->float, 3=write float.
// smem halves: As[3][128][72], Bs[3][128][72]  (72-half row = 144B, pad)
#define HSTR 72
#define TILE_H (128 * HSTR)                  // 9216 halves per stage
#define GEMM_SMEM (6 * TILE_H * 2)           // 110592 bytes

__device__ __forceinline__ void cpasync16(uint32_t dst, const void* src) {
    asm volatile("cp.async.cg.shared.global [%0], [%1], 16;" :: "r"(dst), "l"(src));
}

__device__ __forceinline__ void mmah(float* c, const uint32_t* a, const uint32_t* b) {
    asm volatile(
        "mma.sync.aligned.m16n8k16.row.col.f32.f16.f16.f32 "
        "{%0,%1,%2,%3},{%4,%5,%6,%7},{%8,%9},{%0,%1,%2,%3};"
        : "+f"(c[0]), "+f"(c[1]), "+f"(c[2]), "+f"(c[3])
        : "r"(a[0]), "r"(a[1]), "r"(a[2]), "r"(a[3]), "r"(b[0]), "r"(b[1]));
}

__global__ __launch_bounds__(256, 2)
void gemm_h_kernel(const __half* __restrict__ A, const __half* __restrict__ Wt,
                   const float* __restrict__ bias, void* __restrict__ Cv,
                   int M, int N, int K, int op, const int* __restrict__ start_pos)
{
    extern __shared__ __half hsm[];
    int tid = threadIdx.x, lane = tid & 31, warp = tid >> 5;
    int wm = warp & 1, wn = warp >> 1;          // 2m x 4n, warp tile 64x32
    int m0 = blockIdx.y * 128, n0 = blockIdx.x * 128;

    // copy geometry: per stage 128 rows x 64 halves each for A and B
    int crow = tid >> 1;                 // 0..127
    int cc16 = (tid & 1) * 4;            // chunk col: 0 or 4 (of 8 16B-chunks)
    const __half* aSrc = A  + (size_t)(m0 + crow) * K + cc16 * 8;
    const __half* bSrc = Wt + (size_t)(n0 + crow) * K + cc16 * 8;
    uint32_t asBase = (uint32_t)__cvta_generic_to_shared(hsm);
    uint32_t bsBase = asBase + 3 * TILE_H * 2;
    uint32_t aOff = (uint32_t)(crow * 144 + cc16 * 16);
    uint32_t bOff = aOff;

    float acc[4][4][4];
    #pragma unroll
    for (int i = 0; i < 4; i++)
        #pragma unroll
        for (int j = 0; j < 4; j++)
            #pragma unroll
            for (int r = 0; r < 4; r++) acc[i][j][r] = 0.f;

    int KT = K >> 6;

    #pragma unroll
    for (int s = 0; s < 2; s++) {
        int kk = s * 64;
        #pragma unroll
        for (int i = 0; i < 4; i++)
            cpasync16(asBase + s * (TILE_H * 2) + aOff + (i & 3) * 16, aSrc + kk + i * 8);
        #pragma unroll
        for (int i = 0; i < 4; i++)
            cpasync16(bsBase + s * (TILE_H * 2) + bOff + (i & 3) * 16, bSrc + kk + i * 8);
        asm volatile("cp.async.commit_group;");
    }

    // fragment word offsets (32-bit words, row stride 36 words)
    const uint32_t* aWbase = (const uint32_t*)hsm;
    const uint32_t* bWbase = (const uint32_t*)(hsm + 3 * TILE_H);
    int aRow = wm * 64 + (lane >> 2);
    int bRow = wn * 32 + (lane >> 2);
    int kq   = lane & 3;

    for (int kt = 0; kt < KT; ++kt) {
        asm volatile("cp.async.wait_group 1;" ::: "memory");
        __syncthreads();

        if (kt + 2 < KT) {
            int s = (kt + 2) % 3;
            int kk = (kt + 2) * 64;
            #pragma unroll
            for (int i = 0; i < 4; i++)
                cpasync16(asBase + s * (TILE_H * 2) + aOff + (i & 3) * 16, aSrc + kk + i * 8);
            #pragma unroll
            for (int i = 0; i < 4; i++)
                cpasync16(bsBase + s * (TILE_H * 2) + bOff + (i & 3) * 16, bSrc + kk + i * 8);
        }
        asm volatile("cp.async.commit_group;");

        const uint32_t* aW = aWbase + (kt % 3) * (TILE_H / 2);
        const uint32_t* bW = bWbase + (kt % 3) * (TILE_H / 2);

        #pragma unroll
        for (int ks = 0; ks < 4; ++ks) {
            uint32_t af[4][4], bf[4][2];
            #pragma unroll
            for (int im = 0; im < 4; im++) {
                int r = aRow + im * 16;
                af[im][0] = aW[(r)     * 36 + ks * 8 + kq];
                af[im][1] = aW[(r + 8) * 36 + ks * 8 + kq];
                af[im][2] = aW[(r)     * 36 + ks * 8 + 4 + kq];
                af[im][3] = aW[(r + 8) * 36 + ks * 8 + 4 + kq];
            }
            #pragma unroll
            for (int in = 0; in < 4; in++) {
                int n = bRow + in * 8;
                bf[in][0] = bW[n * 36 + ks * 8 + kq];
                bf[in][1] = bW[n * 36 + ks * 8 + 4 + kq];
            }
            #pragma unroll
            for (int im = 0; im < 4; im++)
                #pragma unroll
                for (int in = 0; in < 4; in++)
                    mmah(acc[im][in], af[im], bf[in]);
        }
    }

    // epilogue
    int rbase = m0 + wm * 64 + (lane >> 2);
    int cbase = n0 + wn * 32 + ((lane & 3) << 1);
    #pragma unroll
    for (int im = 0; im < 4; im++) {
        #pragma unroll
        for (int hh = 0; hh < 2; hh++) {
            int row = rbase + im * 16 + hh * 8;
            bool zero = false;
            if (op == 2) zero = (row & 1023) < start_pos[row >> 10];
            #pragma unroll
            for (int in = 0; in < 4; in++) {
                int col = cbase + in * 8;
                float v0 = acc[im][in][hh * 2 + 0] + bias[col];
                float v1 = acc[im][in][hh * 2 + 1] + bias[col + 1];
                if (op == 1) {
                    v0 = 0.5f * v0 * (1.0f + erff(v0 * 0.70710678118654752f));
                    v1 = 0.5f * v1 * (1.0f + erff(v1 * 0.70710678118654752f));
                }
                if (op == 0 || op == 1) {
                    *(__half2*)((__half*)Cv + (size_t)row * N + col) =
                        __floats2half2_rn(v0, v1);
                } else {
                    if (zero) { v0 = 0.f; v1 = 0.f; }
                    float2 o; o.x = v0; o.y = v1;
                    *(float2*)((float*)Cv + (size_t)row * N + col) = o;
                }
            }
        }
    }
}

// --------------- flash attention (tf32 mma, fp16-exact operands) -----------
#define ATLD 68
#define ATTN_SMEM (4 * 64 * ATLD * 4)

__device__ __forceinline__ void mma8(float* c, const uint32_t* a, const uint32_t* b) {
    asm volatile(
        "mma.sync.aligned.m16n8k8.row.col.f32.tf32.tf32.f32 "
        "{%0,%1,%2,%3},{%4,%5,%6,%7},{%8,%9},{%0,%1,%2,%3};"
        : "+f"(c[0]), "+f"(c[1]), "+f"(c[2]), "+f"(c[3])
        : "r"(a[0]), "r"(a[1]), "r"(a[2]), "r"(a[3]), "r"(b[0]), "r"(b[1]));
}

__global__ __launch_bounds__(128)
void attn_tc_kernel(const __half* __restrict__ QKV, __half* __restrict__ O,
                    const int* __restrict__ start_pos)
{
    extern __shared__ float sm[];
    float* sQ = sm;
    float* sK = sQ + 64 * ATLD;
    float* sV = sK + 64 * ATLD;
    float* sP = sV + 64 * ATLD;

    int tid = threadIdx.x, lane = tid & 31, warp = tid >> 5;
    int qt = blockIdx.x, bh = blockIdx.y;
    int b = bh >> 4, h = bh & 15;
    int sp = start_pos[b];
    float slope = exp2f(-0.5f * (float)(h + 1));
    int brow = b * Sz;

    const __half* Qg = QKV + h * 64;
    const __half* Kg = QKV + 1024 + h * 64;
    const __half* Vg = QKV + 2048 + h * 64;

    for (int i = tid; i < 64 * 16; i += 128) {
        int row = i >> 4, d4 = (i & 15) * 4;
        uint2 u = *(const uint2*)(Qg + (size_t)(brow + qt * 64 + row) * QKVN + d4);
        float2 f0 = __half22float2(*(__half2*)&u.x);
        float2 f1 = __half22float2(*(__half2*)&u.y);
        int o = row * ATLD + d4;
        sQ[o + 0] = f0.x * 0.125f; sQ[o + 1] = f0.y * 0.125f;
        sQ[o + 2] = f1.x * 0.125f; sQ[o + 3] = f1.y * 0.125f;
    }

    int qrow = warp * 16 + (lane >> 2);
    int cA   = lane & 3;
    int ig0 = qt * 64 + qrow, ig1 = ig0 + 8;

    float m0 = -1e30f, m1 = -1e30f, l0 = 0.f, l1 = 0.f;
    float oacc[8][4];
    #pragma unroll
    for (int n = 0; n < 8; n++)
        #pragma unroll
        for (int r = 0; r < 4; r++) oacc[n][r] = 0.f;

    int ktmax = (qt * 64 >= sp) ? qt : 15;

    for (int kt = 0; kt <= ktmax; ++kt) {
        __syncthreads();
        for (int i = tid; i < 64 * 16; i += 128) {
            int row = i >> 4, d4 = (i & 15) * 4;
            uint2 uk = *(const uint2*)(Kg + (size_t)(brow + kt * 64 + row) * QKVN + d4);
            uint2 uv = *(const uint2*)(Vg + (size_t)(brow + kt * 64 + row) * QKVN + d4);
            float2 k0 = __half22float2(*(__half2*)&uk.x);
            float2 k1 = __half22float2(*(__half2*)&uk.y);
            float2 v0 = __half22float2(*(__half2*)&uv.x);
            float2 v1 = __half22float2(*(__half2*)&uv.y);
            int o = row * ATLD + d4;
            sK[o + 0] = k0.x; sK[o + 1] = k0.y; sK[o + 2] = k1.x; sK[o + 3] = k1.y;
            sV[o + 0] = v0.x; sV[o + 1] = v0.y; sV[o + 2] = v1.x; sV[o + 3] = v1.y;
        }
        __syncthreads();

        float sacc[8][4];
        #pragma unroll
        for (int n = 0; n < 8; n++)
            #pragma unroll
            for (int r = 0; r < 4; r++) sacc[n][r] = 0.f;

        #pragma unroll
        for (int ks = 0; ks < 8; ++ks) {
            uint32_t ab[4];
            ab[0] = __float_as_uint(sQ[(qrow)     * ATLD + ks * 8 + cA]);
            ab[1] = __float_as_uint(sQ[(qrow + 8) * ATLD + ks * 8 + cA]);
            ab[2] = __float_as_uint(sQ[(qrow)     * ATLD + ks * 8 + 4 + cA]);
            ab[3] = __float_as_uint(sQ[(qrow + 8) * ATLD + ks * 8 + 4 + cA]);
            #pragma unroll
            for (int n = 0; n < 8; n++) {
                uint32_t bf[2];
                bf[0] = __float_as_uint(sK[(n * 8 + (lane >> 2)) * ATLD + ks * 8 + cA]);
                bf[1] = __float_as_uint(sK[(n * 8 + (lane >> 2)) * ATLD + ks * 8 + 4 + cA]);
                mma8(sacc[n], ab, bf);
            }
        }

        #pragma unroll
        for (int n = 0; n < 8; n++) {
            int jg = kt * 64 + n * 8 + cA * 2;
            #pragma unroll
            for (int half = 0; half < 2; half++) {
                int j = jg + half;
                float al = slope * (float)(j - sp);
                bool ok0 = (j <= ig0) || (ig0 < sp) || (j < sp);
                bool ok1 = (j <= ig1) || (ig1 < sp) || (j < sp);
                sacc[n][half]     = ok0 ? sacc[n][half]     + al : -1e30f;
                sacc[n][half + 2] = ok1 ? sacc[n][half + 2] + al : -1e30f;
            }
        }

        float t0 = -1e30f, t1 = -1e30f;
        #pragma unroll
        for (int n = 0; n < 8; n++) {
            t0 = fmaxf(t0, fmaxf(sacc[n][0], sacc[n][1]));
            t1 = fmaxf(t1, fmaxf(sacc[n][2], sacc[n][3]));
        }
        t0 = fmaxf(t0, __shfl_xor_sync(0xffffffffu, t0, 1));
        t0 = fmaxf(t0, __shfl_xor_sync(0xffffffffu, t0, 2));
        t1 = fmaxf(t1, __shfl_xor_sync(0xffffffffu, t1, 1));
        t1 = fmaxf(t1, __shfl_xor_sync(0xffffffffu, t1, 2));

        float mn0 = fmaxf(m0, t0), mn1 = fmaxf(m1, t1);
        float scl0 = __expf(m0 - mn0), scl1 = __expf(m1 - mn1);
        m0 = mn0; m1 = mn1;

        float ls0 = 0.f, ls1 = 0.f;
        #pragma unroll
        for (int n = 0; n < 8; n++) {
            int col = n * 8 + cA * 2;
            float p0 = to_tf32(__expf(sacc[n][0] - mn0));
            float p1 = to_tf32(__expf(sacc[n][1] - mn0));
            float p2 = to_tf32(__expf(sacc[n][2] - mn1));
            float p3 = to_tf32(__expf(sacc[n][3] - mn1));
            ls0 += p0 + p1;
            ls1 += p2 + p3;
            float2 w0; w0.x = p0; w0.y = p1;
            float2 w1; w1.x = p2; w1.y = p3;
            *(float2*)&sP[(qrow)     * ATLD + col] = w0;
            *(float2*)&sP[(qrow + 8) * ATLD + col] = w1;
        }
        ls0 += __shfl_xor_sync(0xffffffffu, ls0, 1);
        ls0 += __shfl_xor_sync(0xffffffffu, ls0, 2);
        ls1 += __shfl_xor_sync(0xffffffffu, ls1, 1);
        ls1 += __shfl_xor_sync(0xffffffffu, ls1, 2);
        l0 = l0 * scl0 + ls0;
        l1 = l1 * scl1 + ls1;

        #pragma unroll
        for (int n = 0; n < 8; n++) {
            oacc[n][0] *= scl0; oacc[n][1] *= scl0;
            oacc[n][2] *= scl1; oacc[n][3] *= scl1;
        }
        __syncwarp();

        #pragma unroll
        for (int ks = 0; ks < 8; ++ks) {
            uint32_t af[4];
            af[0] = __float_as_uint(sP[(qrow)     * ATLD + ks * 8 + cA]);
            af[1] = __float_as_uint(sP[(qrow + 8) * ATLD + ks * 8 + cA]);
            af[2] = __float_as_uint(sP[(qrow)     * ATLD + ks * 8 + 4 + cA]);
            af[3] = __float_as_uint(sP[(qrow + 8) * ATLD + ks * 8 + 4 + cA]);
            #pragma unroll
            for (int n = 0; n < 8; n++) {
                uint32_t bf[2];
                bf[0] = __float_as_uint(sV[(ks * 8 + cA)     * ATLD + n * 8 + (lane >> 2)]);
                bf[1] = __float_as_uint(sV[(ks * 8 + 4 + cA) * ATLD + n * 8 + (lane >> 2)]);
                mma8(oacc[n], af, bf);
            }
        }
        __syncwarp();
    }

    float inv0 = 1.f / l0, inv1 = 1.f / l1;
    size_t orow0 = (size_t)(brow + qt * 64 + qrow) * Hz + h * 64;
    size_t orow1 = orow0 + (size_t)8 * Hz;
    #pragma unroll
    for (int n = 0; n < 8; n++) {
        int col = n * 8 + cA * 2;
        *(__half2*)(O + orow0 + col) = __floats2half2_rn(oacc[n][0] * inv0, oacc[n][1] * inv0);
        *(__half2*)(O + orow1 + col) = __floats2half2_rn(oacc[n][2] * inv1, oacc[n][3] * inv1);
    }
}

// ------------------------ fused residual + layernorm -----------------------
__inline__ __device__ float warp_sum(float v) {
    #pragma unroll
    for (int o = 16; o; o >>= 1) v += __shfl_xor_sync(0xffffffffu, v, o);
    return v;
}

__global__ void add_ln_kernel(float* __restrict__ x, __half* __restrict__ xch,
                              const float* __restrict__ t,
                              const float* __restrict__ g, const float* __restrict__ b)
{
    int row = blockIdx.x;
    int tid = threadIdx.x;
    size_t off = (size_t)row * Hz + tid * 4;

    float4 xv = *(const float4*)(x + off);
    float4 tv = *(const float4*)(t + off);
    float v0 = xv.x + tv.x, v1 = xv.y + tv.y, v2 = xv.z + tv.z, v3 = xv.w + tv.w;

    float s  = v0 + v1 + v2 + v3;
    float s2 = v0 * v0 + v1 * v1 + v2 * v2 + v3 * v3;

    __shared__ float sh1[8], sh2[8];
    int lane = tid & 31, wid = tid >> 5;
    s  = warp_sum(s);
    s2 = warp_sum(s2);
    if (lane == 0) { sh1[wid] = s; sh2[wid] = s2; }
    __syncthreads();
    if (wid == 0) {
        float a = (lane < 8) ? sh1[lane] : 0.f;
        float c = (lane < 8) ? sh2[lane] : 0.f;
        a = warp_sum(a);
        c = warp_sum(c);
        if (lane == 0) { sh1[0] = a; sh2[0] = c; }
    }
    __syncthreads();

    float mu  = sh1[0] * (1.0f / Hz);
    float var = sh2[0] * (1.0f / Hz) - mu * mu;
    float inv = rsqrtf(var + 1e-5f);

    int cbase = tid * 4;
    float4 gv = *(const float4*)(g + cbase);
    float4 bv = *(const float4*)(b + cbase);
    float4 out;
    out.x = (v0 - mu) * inv * gv.x + bv.x;
    out.y = (v1 - mu) * inv * gv.y + bv.y;
    out.z = (v2 - mu) * inv * gv.z + bv.z;
    out.w = (v3 - mu) * inv * gv.w + bv.w;
    *(float4*)(x + off) = out;
    *(__half2*)(xch + off)     = __floats2half2_rn(out.x, out.y);
    *(__half2*)(xch + off + 2) = __floats2half2_rn(out.z, out.w);
}

// --------------------------------- launch ----------------------------------
extern "C" void kernel_launch(void* const* d_in, const int* in_sizes, int n_in,
                              void* d_out, int out_size)
{
    const int*   ids  = (const int*)d_in[0];
    const int*   sp   = (const int*)d_in[1];
    const float* emb  = (const float*)d_in[2];
    const float* Wq   = (const float*)d_in[3];
    const float* bq   = (const float*)d_in[4];
    const float* Wk   = (const float*)d_in[5];
    const float* bk   = (const float*)d_in[6];
    const float* Wv   = (const float*)d_in[7];
    const float* bv   = (const float*)d_in[8];
    const float* Wo   = (const float*)d_in[9];
    const float* bo   = (const float*)d_in[10];
    const float* ln1g = (const float*)d_in[11];
    const float* ln1b = (const float*)d_in[12];
    const float* ln2g = (const float*)d_in[13];
    const float* ln2b = (const float*)d_in[14];
    const float* W1   = (const float*)d_in[15];
    const float* b1   = (const float*)d_in[16];
    const float* W2   = (const float*)d_in[17];
    const float* b2   = (const float*)d_in[18];
    const float* Wf   = (const float*)d_in[19];
    const float* bf   = (const float*)d_in[20];
    float* out = (float*)d_out;

    float *x, *tmp, *bqkv;
    __half *xch, *qkv, *attnc, *ffc, *w;
    cudaGetSymbolAddress((void**)&x,     g_x);
    cudaGetSymbolAddress((void**)&xch,   g_xch);
    cudaGetSymbolAddress((void**)&qkv,   g_qkv);
    cudaGetSymbolAddress((void**)&attnc, g_attnc);
    cudaGetSymbolAddress((void**)&tmp,   g_tmp);
    cudaGetSymbolAddress((void**)&ffc,   g_ffc);
    cudaGetSymbolAddress((void**)&w,     g_w);
    cudaGetSymbolAddress((void**)&bqkv,  g_bqkv);

    cudaFuncSetAttribute(attn_tc_kernel, cudaFuncAttributeMaxDynamicSharedMemorySize, ATTN_SMEM);
    cudaFuncSetAttribute(gemm_h_kernel, cudaFuncAttributeMaxDynamicSharedMemorySize, GEMM_SMEM);

    dim3 tb(32, 8);
    for (int l = 0; l < Lz; ++l) {
        __half* qkvT = w + OFF_QKV + (size_t)l * Hz * QKVN;
        transT_kernel<<<dim3(Hz / 32, Hz / 32), tb>>>(Wq + (size_t)l * Hz * Hz, qkvT,                     Hz, Hz);
        transT_kernel<<<dim3(Hz / 32, Hz / 32), tb>>>(Wk + (size_t)l * Hz * Hz, qkvT + (size_t)1024 * Hz, Hz, Hz);
        transT_kernel<<<dim3(Hz / 32, Hz / 32), tb>>>(Wv + (size_t)l * Hz * Hz, qkvT + (size_t)2048 * Hz, Hz, Hz);
        transT_kernel<<<dim3(Hz / 32, Hz / 32), tb>>>(Wo + (size_t)l * Hz * Hz, w + OFF_WO + (size_t)l * Hz * Hz, Hz, Hz);
        transT_kernel<<<dim3(Hz / 32, DFz / 32), tb>>>(W1 + (size_t)l * Hz * DFz, w + OFF_W1 + (size_t)l * Hz * DFz, Hz, DFz);
        transT_kernel<<<dim3(DFz / 32, Hz / 32), tb>>>(W2 + (size_t)l * DFz * Hz, w + OFF_W2 + (size_t)l * DFz * Hz, DFz, Hz);
    }
    transT_kernel<<<dim3(Hz / 32, Vz / 32), tb>>>(Wf, w + OFF_WF, Hz, Vz);
    cvt_bias_kernel<<<(Lz * QKVN) / 256, 256>>>(bq, bk, bv, bqkv);

    embed_kernel<<<Mz, 256>>>(ids, emb, x, xch);

    for (int l = 0; l < Lz; ++l) {
        gemm_h_kernel<<<dim3(QKVN / 128, Mz / 128), 256, GEMM_SMEM>>>(
            xch, w + OFF_QKV + (size_t)l * Hz * QKVN, bqkv + l * QKVN, qkv,
            Mz, QKVN, Hz, 0, sp);

        attn_tc_kernel<<<dim3(Sz / 64, Bz * NHz), 128, ATTN_SMEM>>>(qkv, attnc, sp);

        gemm_h_kernel<<<dim3(Hz / 128, Mz / 128), 256, GEMM_SMEM>>>(
            attnc, w + OFF_WO + (size_t)l * Hz * Hz, bo + l * Hz, tmp,
            Mz, Hz, Hz, 3, sp);
        add_ln_kernel<<<Mz, 256>>>(x, xch, tmp, ln1g + l * Hz, ln1b + l * Hz);

        gemm_h_kernel<<<dim3(DFz / 128, Mz / 128), 256, GEMM_SMEM>>>(
            xch, w + OFF_W1 + (size_t)l * Hz * DFz, b1 + l * DFz, ffc,
            Mz, DFz, Hz, 1, sp);
        gemm_h_kernel<<<dim3(Hz / 128, Mz / 128), 256, GEMM_SMEM>>>(
            ffc, w + OFF_W2 + (size_t)l * DFz * Hz, b2 + l * Hz, tmp,
            Mz, Hz, DFz, 3, sp);
        add_ln_kernel<<<Mz, 256>>>(x, xch, tmp, ln2g + l * Hz, ln2b + l * Hz);
    }

    gemm_h_kernel<<<dim3(Vz / 128, Mz / 128), 256, GEMM_SMEM>>>(
        xch, w + OFF_WF, bf, out, Mz, Vz, Hz, 2, sp);
}

// round 8
// speedup vs baseline: 5.4671x; 1.0311x over previous
#include <cuda_runtime.h>
#include <cuda_fp16.h>
#include <math.h>
#include <stdint.h>

// ---------------------------------------------------------------------------
// TidalTransformer: B=4, S=1024, H=1024, NH=16, DK=64, DF=4096, L=4, V=32000
// Round 8: fp16 GEMMs with ldmatrix fragment loads; fp16 flash attention
//          (m16n8k16, transposed V in smem); fp32 residual stream; fused LN.
// ---------------------------------------------------------------------------

#define Bz   4
#define Sz   1024
#define Hz   1024
#define NHz  16
#define DKz  64
#define DFz  4096
#define Lz   4
#define Vz   32000
#define Mz   (Bz * Sz)
#define QKVN 3072

// ------------------------- scratch (device globals) ------------------------
__device__ float  g_x   [(size_t)Mz * Hz];
__device__ __half g_xch [(size_t)Mz * Hz];
__device__ __half g_qkv [(size_t)Mz * QKVN];
__device__ __half g_attnc[(size_t)Mz * Hz];
__device__ float  g_tmp [(size_t)Mz * Hz];
__device__ __half g_ffc [(size_t)Mz * DFz];

#define OFF_QKV 0
#define OFF_WO  ((size_t)12582912)
#define OFF_W1  ((size_t)16777216)
#define OFF_W2  ((size_t)33554432)
#define OFF_WF  ((size_t)50331648)
__device__ __half g_w[(size_t)83099648];
__device__ float  g_bqkv[Lz * QKVN];

// --------------------- transpose + fp16 convert ----------------------------
__global__ void transT_kernel(const float* __restrict__ src, __half* __restrict__ dst,
                              int K, int N)
{
    __shared__ float t[32][33];
    int kb = blockIdx.x * 32, nb = blockIdx.y * 32;
    int tx = threadIdx.x, ty = threadIdx.y;
    #pragma unroll
    for (int i = 0; i < 4; i++)
        t[ty + i * 8][tx] = src[(size_t)(kb + ty + i * 8) * N + nb + tx];
    __syncthreads();
    #pragma unroll
    for (int i = 0; i < 4; i++)
        dst[(size_t)(nb + ty + i * 8) * K + kb + tx] = __float2half_rn(t[tx][ty + i * 8]);
}

__global__ void cvt_bias_kernel(const float* __restrict__ bq, const float* __restrict__ bk,
                                const float* __restrict__ bv, float* __restrict__ dst)
{
    int i = blockIdx.x * 256 + threadIdx.x;
    int n = i % QKVN, l = i / QKVN;
    float v;
    if (n < 1024)       v = bq[l * 1024 + n];
    else if (n < 2048)  v = bk[l * 1024 + n - 1024];
    else                v = bv[l * 1024 + n - 2048];
    dst[i] = v;
}

// ------------------------------- embedding ---------------------------------
__global__ void embed_kernel(const int* __restrict__ ids,
                             const float* __restrict__ emb,
                             float* __restrict__ x, __half* __restrict__ xch)
{
    int row = blockIdx.x;
    int tid = threadIdx.x;
    int id  = ids[row];
    float4 v = *(const float4*)(emb + (size_t)id * Hz + tid * 4);
    v.x *= 32.0f; v.y *= 32.0f; v.z *= 32.0f; v.w *= 32.0f;
    *(float4*)(x + (size_t)row * Hz + tid * 4) = v;
    *(__half2*)(xch + (size_t)row * Hz + tid * 4)     = __floats2half2_rn(v.x, v.y);
    *(__half2*)(xch + (size_t)row * Hz + tid * 4 + 2) = __floats2half2_rn(v.z, v.w);
}

// ---------------------------- mma / ldmatrix -------------------------------
__device__ __forceinline__ void mmah(float* c, const uint32_t* a, const uint32_t* b) {
    asm volatile(
        "mma.sync.aligned.m16n8k16.row.col.f32.f16.f16.f32 "
        "{%0,%1,%2,%3},{%4,%5,%6,%7},{%8,%9},{%0,%1,%2,%3};"
        : "+f"(c[0]), "+f"(c[1]), "+f"(c[2]), "+f"(c[3])
        : "r"(a[0]), "r"(a[1]), "r"(a[2]), "r"(a[3]), "r"(b[0]), "r"(b[1]));
}
__device__ __forceinline__ void ldsm4(uint32_t addr, uint32_t& r0, uint32_t& r1,
                                      uint32_t& r2, uint32_t& r3) {
    asm volatile("ldmatrix.sync.aligned.m8n8.x4.shared.b16 {%0,%1,%2,%3}, [%4];"
                 : "=r"(r0), "=r"(r1), "=r"(r2), "=r"(r3) : "r"(addr));
}
__device__ __forceinline__ void cpasync16(uint32_t dst, const void* src) {
    asm volatile("cp.async.cg.shared.global [%0], [%1], 16;" :: "r"(dst), "l"(src));
}

// ------------------ fp16 GEMM: 128x128 tile, BK=64, 3-stage ----------------
#define HSTR 72
#define TILE_H (128 * HSTR)
#define GEMM_SMEM (6 * TILE_H * 2)

__global__ __launch_bounds__(256, 2)
void gemm_h_kernel(const __half* __restrict__ A, const __half* __restrict__ Wt,
                   const float* __restrict__ bias, void* __restrict__ Cv,
                   int M, int N, int K, int op, const int* __restrict__ start_pos)
{
    extern __shared__ __half hsm[];
    int tid = threadIdx.x, lane = tid & 31, warp = tid >> 5;
    int wm = warp & 1, wn = warp >> 1;
    int m0 = blockIdx.y * 128, n0 = blockIdx.x * 128;

    int crow = tid >> 1;
    int cc16 = (tid & 1) * 4;
    const __half* aSrc = A  + (size_t)(m0 + crow) * K + cc16 * 8;
    const __half* bSrc = Wt + (size_t)(n0 + crow) * K + cc16 * 8;
    uint32_t asBase = (uint32_t)__cvta_generic_to_shared(hsm);
    uint32_t bsBase = asBase + 3 * TILE_H * 2;
    uint32_t cOff = (uint32_t)(crow * 144 + cc16 * 16);

    float acc[4][4][4];
    #pragma unroll
    for (int i = 0; i < 4; i++)
        #pragma unroll
        for (int j = 0; j < 4; j++)
            #pragma unroll
            for (int r = 0; r < 4; r++) acc[i][j][r] = 0.f;

    int KT = K >> 6;

    #pragma unroll
    for (int s = 0; s < 2; s++) {
        int kk = s * 64;
        #pragma unroll
        for (int i = 0; i < 4; i++)
            cpasync16(asBase + s * (TILE_H * 2) + cOff + i * 16, aSrc + kk + i * 8);
        #pragma unroll
        for (int i = 0; i < 4; i++)
            cpasync16(bsBase + s * (TILE_H * 2) + cOff + i * 16, bSrc + kk + i * 8);
        asm volatile("cp.async.commit_group;");
    }

    // ldmatrix lane offsets (bytes): row = base + (lane&15), k-half select = lane>>4
    uint32_t aLd = (uint32_t)((wm * 64 + (lane & 15)) * 144 + (lane >> 4) * 16);
    uint32_t bLd = (uint32_t)((wn * 32 + (lane & 15)) * 144 + (lane >> 4) * 16);

    for (int kt = 0; kt < KT; ++kt) {
        asm volatile("cp.async.wait_group 1;" ::: "memory");
        __syncthreads();

        if (kt + 2 < KT) {
            int s = (kt + 2) % 3;
            int kk = (kt + 2) * 64;
            #pragma unroll
            for (int i = 0; i < 4; i++)
                cpasync16(asBase + s * (TILE_H * 2) + cOff + i * 16, aSrc + kk + i * 8);
            #pragma unroll
            for (int i = 0; i < 4; i++)
                cpasync16(bsBase + s * (TILE_H * 2) + cOff + i * 16, bSrc + kk + i * 8);
        }
        asm volatile("cp.async.commit_group;");

        uint32_t aSB = asBase + (kt % 3) * (TILE_H * 2);
        uint32_t bSB = bsBase + (kt % 3) * (TILE_H * 2);

        #pragma unroll
        for (int ks = 0; ks < 4; ++ks) {
            uint32_t afr[4][4], br[2][4];
            #pragma unroll
            for (int im = 0; im < 4; im++)
                ldsm4(aSB + aLd + im * 2304 + ks * 32,
                      afr[im][0], afr[im][1], afr[im][2], afr[im][3]);
            #pragma unroll
            for (int p = 0; p < 2; p++)
                ldsm4(bSB + bLd + p * 2304 + ks * 32,
                      br[p][0], br[p][1], br[p][2], br[p][3]);
            #pragma unroll
            for (int im = 0; im < 4; im++)
                #pragma unroll
                for (int in = 0; in < 4; in++) {
                    uint32_t bb[2] = { br[in >> 1][in & 1], br[in >> 1][(in & 1) + 2] };
                    mmah(acc[im][in], afr[im], bb);
                }
        }
    }

    // epilogue
    int rbase = m0 + wm * 64 + (lane >> 2);
    int cbase = n0 + wn * 32 + ((lane & 3) << 1);
    #pragma unroll
    for (int im = 0; im < 4; im++) {
        #pragma unroll
        for (int hh = 0; hh < 2; hh++) {
            int row = rbase + im * 16 + hh * 8;
            bool zero = false;
            if (op == 2) zero = (row & 1023) < start_pos[row >> 10];
            #pragma unroll
            for (int in = 0; in < 4; in++) {
                int col = cbase + in * 8;
                float v0 = acc[im][in][hh * 2 + 0] + bias[col];
                float v1 = acc[im][in][hh * 2 + 1] + bias[col + 1];
                if (op == 1) {
                    v0 = 0.5f * v0 * (1.0f + erff(v0 * 0.70710678118654752f));
                    v1 = 0.5f * v1 * (1.0f + erff(v1 * 0.70710678118654752f));
                }
                if (op == 0 || op == 1) {
                    *(__half2*)((__half*)Cv + (size_t)row * N + col) =
                        __floats2half2_rn(v0, v1);
                } else {
                    if (zero) { v0 = 0.f; v1 = 0.f; }
                    float2 o; o.x = v0; o.y = v1;
                    *(float2*)((float*)Cv + (size_t)row * N + col) = o;
                }
            }
        }
    }
}

// ---------------------- fp16 flash attention -------------------------------
// 64 q rows, 4 warps (m16 x n64). QK + PV via mma.m16n8k16.f16, fp32 accum.
// V stored transposed in smem (sVt[d][k]) so PV B-operand is k-contiguous.
#define AH 72

__global__ __launch_bounds__(128)
void attn_h_kernel(const __half* __restrict__ QKV, __half* __restrict__ O,
                   const int* __restrict__ start_pos)
{
    __shared__ __half sQ[64 * AH], sK[64 * AH], sVt[64 * AH], sP[64 * AH];
    const uint32_t* qW = (const uint32_t*)sQ;
    const uint32_t* kW = (const uint32_t*)sK;
    const uint32_t* vW = (const uint32_t*)sVt;
    uint32_t* pW = (uint32_t*)sP;

    int tid = threadIdx.x, lane = tid & 31, warp = tid >> 5;
    int qt = blockIdx.x, bh = blockIdx.y;
    int b = bh >> 4, h = bh & 15;
    int sp = start_pos[b];
    float slope = exp2f(-0.5f * (float)(h + 1));
    int brow = b * Sz;

    const __half* Qg = QKV + h * 64;
    const __half* Kg = QKV + 1024 + h * 64;
    const __half* Vg = QKV + 2048 + h * 64;

    const __half2 hscale = __float2half2_rn(0.125f);
    for (int i = tid; i < 64 * 16; i += 128) {
        int row = i >> 4, d4 = (i & 15) * 4;
        uint2 u = *(const uint2*)(Qg + (size_t)(brow + qt * 64 + row) * QKVN + d4);
        __half2 h0 = __hmul2(*(__half2*)&u.x, hscale);
        __half2 h1 = __hmul2(*(__half2*)&u.y, hscale);
        uint2 o; o.x = *(uint32_t*)&h0; o.y = *(uint32_t*)&h1;
        *(uint2*)(sQ + row * AH + d4) = o;
    }

    int qrow = warp * 16 + (lane >> 2);
    int cA   = lane & 3;
    int kq   = lane & 3;
    int ig0 = qt * 64 + qrow, ig1 = ig0 + 8;

    float m0 = -1e30f, m1 = -1e30f, l0 = 0.f, l1 = 0.f;
    float oacc[8][4];
    #pragma unroll
    for (int n = 0; n < 8; n++)
        #pragma unroll
        for (int r = 0; r < 4; r++) oacc[n][r] = 0.f;

    int ktmax = (qt * 64 >= sp) ? qt : 15;

    for (int kt = 0; kt <= ktmax; ++kt) {
        __syncthreads();
        for (int i = tid; i < 64 * 16; i += 128) {
            int row = i >> 4, d4 = (i & 15) * 4;
            uint2 uk = *(const uint2*)(Kg + (size_t)(brow + kt * 64 + row) * QKVN + d4);
            *(uint2*)(sK + row * AH + d4) = uk;
            uint2 uv = *(const uint2*)(Vg + (size_t)(brow + kt * 64 + row) * QKVN + d4);
            __half vh[4];
            *(uint2*)vh = uv;
            #pragma unroll
            for (int j = 0; j < 4; j++)
                sVt[(d4 + j) * AH + row] = vh[j];
        }
        __syncthreads();

        // ---- scores = Q @ K^T ----
        float sacc[8][4];
        #pragma unroll
        for (int n = 0; n < 8; n++)
            #pragma unroll
            for (int r = 0; r < 4; r++) sacc[n][r] = 0.f;

        #pragma unroll
        for (int ks = 0; ks < 4; ++ks) {
            uint32_t af[4];
            af[0] = qW[(qrow)     * 36 + ks * 8 + kq];
            af[1] = qW[(qrow + 8) * 36 + ks * 8 + kq];
            af[2] = qW[(qrow)     * 36 + ks * 8 + 4 + kq];
            af[3] = qW[(qrow + 8) * 36 + ks * 8 + 4 + kq];
            #pragma unroll
            for (int n = 0; n < 8; n++) {
                int nr = n * 8 + (lane >> 2);
                uint32_t bf[2];
                bf[0] = kW[nr * 36 + ks * 8 + kq];
                bf[1] = kW[nr * 36 + ks * 8 + 4 + kq];
                mmah(sacc[n], af, bf);
            }
        }

        // ---- alibi + mask ----
        #pragma unroll
        for (int n = 0; n < 8; n++) {
            int jg = kt * 64 + n * 8 + cA * 2;
            #pragma unroll
            for (int half = 0; half < 2; half++) {
                int j = jg + half;
                float al = slope * (float)(j - sp);
                bool ok0 = (j <= ig0) || (ig0 < sp) || (j < sp);
                bool ok1 = (j <= ig1) || (ig1 < sp) || (j < sp);
                sacc[n][half]     = ok0 ? sacc[n][half]     + al : -1e30f;
                sacc[n][half + 2] = ok1 ? sacc[n][half + 2] + al : -1e30f;
            }
        }

        // ---- row max ----
        float t0 = -1e30f, t1 = -1e30f;
        #pragma unroll
        for (int n = 0; n < 8; n++) {
            t0 = fmaxf(t0, fmaxf(sacc[n][0], sacc[n][1]));
            t1 = fmaxf(t1, fmaxf(sacc[n][2], sacc[n][3]));
        }
        t0 = fmaxf(t0, __shfl_xor_sync(0xffffffffu, t0, 1));
        t0 = fmaxf(t0, __shfl_xor_sync(0xffffffffu, t0, 2));
        t1 = fmaxf(t1, __shfl_xor_sync(0xffffffffu, t1, 1));
        t1 = fmaxf(t1, __shfl_xor_sync(0xffffffffu, t1, 2));

        float mn0 = fmaxf(m0, t0), mn1 = fmaxf(m1, t1);
        float scl0 = __expf(m0 - mn0), scl1 = __expf(m1 - mn1);
        m0 = mn0; m1 = mn1;

        // ---- exp, P store (fp16), partial l from rounded P ----
        float ls0 = 0.f, ls1 = 0.f;
        #pragma unroll
        for (int n = 0; n < 8; n++) {
            __half2 hp0 = __floats2half2_rn(__expf(sacc[n][0] - mn0),
                                            __expf(sacc[n][1] - mn0));
            __half2 hp1 = __floats2half2_rn(__expf(sacc[n][2] - mn1),
                                            __expf(sacc[n][3] - mn1));
            float2 f0 = __half22float2(hp0);
            float2 f1 = __half22float2(hp1);
            ls0 += f0.x + f0.y;
            ls1 += f1.x + f1.y;
            pW[(qrow)     * 36 + n * 4 + cA] = *(uint32_t*)&hp0;
            pW[(qrow + 8) * 36 + n * 4 + cA] = *(uint32_t*)&hp1;
        }
        ls0 += __shfl_xor_sync(0xffffffffu, ls0, 1);
        ls0 += __shfl_xor_sync(0xffffffffu, ls0, 2);
        ls1 += __shfl_xor_sync(0xffffffffu, ls1, 1);
        ls1 += __shfl_xor_sync(0xffffffffu, ls1, 2);
        l0 = l0 * scl0 + ls0;
        l1 = l1 * scl1 + ls1;

        #pragma unroll
        for (int n = 0; n < 8; n++) {
            oacc[n][0] *= scl0; oacc[n][1] *= scl0;
            oacc[n][2] *= scl1; oacc[n][3] *= scl1;
        }
        __syncwarp();

        // ---- O += P @ V  (A = P rows, B = Vt[d][k]) ----
        #pragma unroll
        for (int ks = 0; ks < 4; ++ks) {
            uint32_t af[4];
            af[0] = pW[(qrow)     * 36 + ks * 8 + kq];
            af[1] = pW[(qrow + 8) * 36 + ks * 8 + kq];
            af[2] = pW[(qrow)     * 36 + ks * 8 + 4 + kq];
            af[3] = pW[(qrow + 8) * 36 + ks * 8 + 4 + kq];
            #pragma unroll
            for (int n = 0; n < 8; n++) {
                int nr = n * 8 + (lane >> 2);
                uint32_t bf[2];
                bf[0] = vW[nr * 36 + ks * 8 + kq];
                bf[1] = vW[nr * 36 + ks * 8 + 4 + kq];
                mmah(oacc[n], af, bf);
            }
        }
        __syncwarp();
    }

    float inv0 = 1.f / l0, inv1 = 1.f / l1;
    size_t orow0 = (size_t)(brow + qt * 64 + qrow) * Hz + h * 64;
    size_t orow1 = orow0 + (size_t)8 * Hz;
    #pragma unroll
    for (int n = 0; n < 8; n++) {
        int col = n * 8 + cA * 2;
        *(__half2*)(O + orow0 + col) = __floats2half2_rn(oacc[n][0] * inv0, oacc[n][1] * inv0);
        *(__half2*)(O + orow1 + col) = __floats2half2_rn(oacc[n][2] * inv1, oacc[n][3] * inv1);
    }
}

// ------------------------ fused residual + layernorm -----------------------
__inline__ __device__ float warp_sum(float v) {
    #pragma unroll
    for (int o = 16; o; o >>= 1) v += __shfl_xor_sync(0xffffffffu, v, o);
    return v;
}

__global__ void add_ln_kernel(float* __restrict__ x, __half* __restrict__ xch,
                              const float* __restrict__ t,
                              const float* __restrict__ g, const float* __restrict__ b)
{
    int row = blockIdx.x;
    int tid = threadIdx.x;
    size_t off = (size_t)row * Hz + tid * 4;

    float4 xv = *(const float4*)(x + off);
    float4 tv = *(const float4*)(t + off);
    float v0 = xv.x + tv.x, v1 = xv.y + tv.y, v2 = xv.z + tv.z, v3 = xv.w + tv.w;

    float s  = v0 + v1 + v2 + v3;
    float s2 = v0 * v0 + v1 * v1 + v2 * v2 + v3 * v3;

    __shared__ float sh1[8], sh2[8];
    int lane = tid & 31, wid = tid >> 5;
    s  = warp_sum(s);
    s2 = warp_sum(s2);
    if (lane == 0) { sh1[wid] = s; sh2[wid] = s2; }
    __syncthreads();
    if (wid == 0) {
        float a = (lane < 8) ? sh1[lane] : 0.f;
        float c = (lane < 8) ? sh2[lane] : 0.f;
        a = warp_sum(a);
        c = warp_sum(c);
        if (lane == 0) { sh1[0] = a; sh2[0] = c; }
    }
    __syncthreads();

    float mu  = sh1[0] * (1.0f / Hz);
    float var = sh2[0] * (1.0f / Hz) - mu * mu;
    float inv = rsqrtf(var + 1e-5f);

    int cbase = tid * 4;
    float4 gv = *(const float4*)(g + cbase);
    float4 bv = *(const float4*)(b + cbase);
    float4 out;
    out.x = (v0 - mu) * inv * gv.x + bv.x;
    out.y = (v1 - mu) * inv * gv.y + bv.y;
    out.z = (v2 - mu) * inv * gv.z + bv.z;
    out.w = (v3 - mu) * inv * gv.w + bv.w;
    *(float4*)(x + off) = out;
    *(__half2*)(xch + off)     = __floats2half2_rn(out.x, out.y);
    *(__half2*)(xch + off + 2) = __floats2half2_rn(out.z, out.w);
}

// --------------------------------- launch ----------------------------------
extern "C" void kernel_launch(void* const* d_in, const int* in_sizes, int n_in,
                              void* d_out, int out_size)
{
    const int*   ids  = (const int*)d_in[0];
    const int*   sp   = (const int*)d_in[1];
    const float* emb  = (const float*)d_in[2];
    const float* Wq   = (const float*)d_in[3];
    const float* bq   = (const float*)d_in[4];
    const float* Wk   = (const float*)d_in[5];
    const float* bk   = (const float*)d_in[6];
    const float* Wv   = (const float*)d_in[7];
    const float* bv   = (const float*)d_in[8];
    const float* Wo   = (const float*)d_in[9];
    const float* bo   = (const float*)d_in[10];
    const float* ln1g = (const float*)d_in[11];
    const float* ln1b = (const float*)d_in[12];
    const float* ln2g = (const float*)d_in[13];
    const float* ln2b = (const float*)d_in[14];
    const float* W1   = (const float*)d_in[15];
    const float* b1   = (const float*)d_in[16];
    const float* W2   = (const float*)d_in[17];
    const float* b2   = (const float*)d_in[18];
    const float* Wf   = (const float*)d_in[19];
    const float* bf   = (const float*)d_in[20];
    float* out = (float*)d_out;

    float *x, *tmp, *bqkv;
    __half *xch, *qkv, *attnc, *ffc, *w;
    cudaGetSymbolAddress((void**)&x,     g_x);
    cudaGetSymbolAddress((void**)&xch,   g_xch);
    cudaGetSymbolAddress((void**)&qkv,   g_qkv);
    cudaGetSymbolAddress((void**)&attnc, g_attnc);
    cudaGetSymbolAddress((void**)&tmp,   g_tmp);
    cudaGetSymbolAddress((void**)&ffc,   g_ffc);
    cudaGetSymbolAddress((void**)&w,     g_w);
    cudaGetSymbolAddress((void**)&bqkv,  g_bqkv);

    cudaFuncSetAttribute(gemm_h_kernel, cudaFuncAttributeMaxDynamicSharedMemorySize, GEMM_SMEM);

    dim3 tb(32, 8);
    for (int l = 0; l < Lz; ++l) {
        __half* qkvT = w + OFF_QKV + (size_t)l * Hz * QKVN;
        transT_kernel<<<dim3(Hz / 32, Hz / 32), tb>>>(Wq + (size_t)l * Hz * Hz, qkvT,                     Hz, Hz);
        transT_kernel<<<dim3(Hz / 32, Hz / 32), tb>>>(Wk + (size_t)l * Hz * Hz, qkvT + (size_t)1024 * Hz, Hz, Hz);
        transT_kernel<<<dim3(Hz / 32, Hz / 32), tb>>>(Wv + (size_t)l * Hz * Hz, qkvT + (size_t)2048 * Hz, Hz, Hz);
        transT_kernel<<<dim3(Hz / 32, Hz / 32), tb>>>(Wo + (size_t)l * Hz * Hz, w + OFF_WO + (size_t)l * Hz * Hz, Hz, Hz);
        transT_kernel<<<dim3(Hz / 32, DFz / 32), tb>>>(W1 + (size_t)l * Hz * DFz, w + OFF_W1 + (size_t)l * Hz * DFz, Hz, DFz);
        transT_kernel<<<dim3(DFz / 32, Hz / 32), tb>>>(W2 + (size_t)l * DFz * Hz, w + OFF_W2 + (size_t)l * DFz * Hz, DFz, Hz);
    }
    transT_kernel<<<dim3(Hz / 32, Vz / 32), tb>>>(Wf, w + OFF_WF, Hz, Vz);
    cvt_bias_kernel<<<(Lz * QKVN) / 256, 256>>>(bq, bk, bv, bqkv);

    embed_kernel<<<Mz, 256>>>(ids, emb, x, xch);

    for (int l = 0; l < Lz; ++l) {
        gemm_h_kernel<<<dim3(QKVN / 128, Mz / 128), 256, GEMM_SMEM>>>(
            xch, w + OFF_QKV + (size_t)l * Hz * QKVN, bqkv + l * QKVN, qkv,
            Mz, QKVN, Hz, 0, sp);

        attn_h_kernel<<<dim3(Sz / 64, Bz * NHz), 128>>>(qkv, attnc, sp);

        gemm_h_kernel<<<dim3(Hz / 128, Mz / 128), 256, GEMM_SMEM>>>(
            attnc, w + OFF_WO + (size_t)l * Hz * Hz, bo + l * Hz, tmp,
            Mz, Hz, Hz, 3, sp);
        add_ln_kernel<<<Mz, 256>>>(x, xch, tmp, ln1g + l * Hz, ln1b + l * Hz);

        gemm_h_kernel<<<dim3(DFz / 128, Mz / 128), 256, GEMM_SMEM>>>(
            xch, w + OFF_W1 + (size_t)l * Hz * DFz, b1 + l * DFz, ffc,
            Mz, DFz, Hz, 1, sp);
        gemm_h_kernel<<<dim3(Hz / 128, Mz / 128), 256, GEMM_SMEM>>>(
            ffc, w + OFF_W2 + (size_t)l * DFz * Hz, b2 + l * Hz, tmp,
            Mz, Hz, DFz, 3, sp);
        add_ln_kernel<<<Mz, 256>>>(x, xch, tmp, ln2g + l * Hz, ln2b + l * Hz);
    }

    gemm_h_kernel<<<dim3(Vz / 128, Mz / 128), 256, GEMM_SMEM>>>(
        xch, w + OFF_WF, bf, out, Mz, Vz, Hz, 2, sp);
}

// round 9
// speedup vs baseline: 5.5015x; 1.0063x over previous
#include <cuda_runtime.h>
#include <cuda_fp16.h>
#include <math.h>
#include <stdint.h>

// ---------------------------------------------------------------------------
// TidalTransformer: B=4, S=1024, H=1024, NH=16, DK=64, DF=4096, L=4, V=32000
// Round 9: M-fastest GEMM grids (L2 weight reuse on logits), ldmatrix
//          attention fragments, batched weight-prep, fp16 GEMM/attention.
// ---------------------------------------------------------------------------

#define Bz   4
#define Sz   1024
#define Hz   1024
#define NHz  16
#define DKz  64
#define DFz  4096
#define Lz   4
#define Vz   32000
#define Mz   (Bz * Sz)
#define QKVN 3072

// ------------------------- scratch (device globals) ------------------------
__device__ float  g_x   [(size_t)Mz * Hz];
__device__ __half g_xch [(size_t)Mz * Hz];
__device__ __half g_qkv [(size_t)Mz * QKVN];
__device__ __half g_attnc[(size_t)Mz * Hz];
__device__ float  g_tmp [(size_t)Mz * Hz];
__device__ __half g_ffc [(size_t)Mz * DFz];

#define OFF_QKV 0
#define OFF_WO  ((size_t)12582912)
#define OFF_W1  ((size_t)16777216)
#define OFF_W2  ((size_t)33554432)
#define OFF_WF  ((size_t)50331648)
__device__ __half g_w[(size_t)83099648];
__device__ float  g_bqkv[Lz * QKVN];

// --------------------- batched transpose + fp16 convert --------------------
// src [K, N] fp32 row-major (+ l*sstride) -> dst [N, K] fp16 (+ l*dstride)
__global__ void transT_b_kernel(const float* __restrict__ src0, __half* __restrict__ dst0,
                                int K, int N, size_t sstride, size_t dstride)
{
    __shared__ float t[32][33];
    const float* src = src0 + (size_t)blockIdx.z * sstride;
    __half* dst = dst0 + (size_t)blockIdx.z * dstride;
    int kb = blockIdx.x * 32, nb = blockIdx.y * 32;
    int tx = threadIdx.x, ty = threadIdx.y;
    #pragma unroll
    for (int i = 0; i < 4; i++)
        t[ty + i * 8][tx] = src[(size_t)(kb + ty + i * 8) * N + nb + tx];
    __syncthreads();
    #pragma unroll
    for (int i = 0; i < 4; i++)
        dst[(size_t)(nb + ty + i * 8) * K + kb + tx] = __float2half_rn(t[tx][ty + i * 8]);
}

__global__ void cvt_bias_kernel(const float* __restrict__ bq, const float* __restrict__ bk,
                                const float* __restrict__ bv, float* __restrict__ dst)
{
    int i = blockIdx.x * 256 + threadIdx.x;
    int n = i % QKVN, l = i / QKVN;
    float v;
    if (n < 1024)       v = bq[l * 1024 + n];
    else if (n < 2048)  v = bk[l * 1024 + n - 1024];
    else                v = bv[l * 1024 + n - 2048];
    dst[i] = v;
}

// ------------------------------- embedding ---------------------------------
__global__ void embed_kernel(const int* __restrict__ ids,
                             const float* __restrict__ emb,
                             float* __restrict__ x, __half* __restrict__ xch)
{
    int row = blockIdx.x;
    int tid = threadIdx.x;
    int id  = ids[row];
    float4 v = *(const float4*)(emb + (size_t)id * Hz + tid * 4);
    v.x *= 32.0f; v.y *= 32.0f; v.z *= 32.0f; v.w *= 32.0f;
    *(float4*)(x + (size_t)row * Hz + tid * 4) = v;
    *(__half2*)(xch + (size_t)row * Hz + tid * 4)     = __floats2half2_rn(v.x, v.y);
    *(__half2*)(xch + (size_t)row * Hz + tid * 4 + 2) = __floats2half2_rn(v.z, v.w);
}

// ---------------------------- mma / ldmatrix -------------------------------
__device__ __forceinline__ void mmah(float* c, const uint32_t* a, const uint32_t* b) {
    asm volatile(
        "mma.sync.aligned.m16n8k16.row.col.f32.f16.f16.f32 "
        "{%0,%1,%2,%3},{%4,%5,%6,%7},{%8,%9},{%0,%1,%2,%3};"
        : "+f"(c[0]), "+f"(c[1]), "+f"(c[2]), "+f"(c[3])
        : "r"(a[0]), "r"(a[1]), "r"(a[2]), "r"(a[3]), "r"(b[0]), "r"(b[1]));
}
__device__ __forceinline__ void ldsm4(uint32_t addr, uint32_t& r0, uint32_t& r1,
                                      uint32_t& r2, uint32_t& r3) {
    asm volatile("ldmatrix.sync.aligned.m8n8.x4.shared.b16 {%0,%1,%2,%3}, [%4];"
                 : "=r"(r0), "=r"(r1), "=r"(r2), "=r"(r3) : "r"(addr));
}
__device__ __forceinline__ void cpasync16(uint32_t dst, const void* src) {
    asm volatile("cp.async.cg.shared.global [%0], [%1], 16;" :: "r"(dst), "l"(src));
}

// ------------------ fp16 GEMM: 128x128 tile, BK=64, 3-stage ----------------
// Grid: blockIdx.x = M-tile (fast), blockIdx.y = N-tile  => L2 weight reuse.
#define HSTR 72
#define TILE_H (128 * HSTR)
#define GEMM_SMEM (6 * TILE_H * 2)

__global__ __launch_bounds__(256, 2)
void gemm_h_kernel(const __half* __restrict__ A, const __half* __restrict__ Wt,
                   const float* __restrict__ bias, void* __restrict__ Cv,
                   int M, int N, int K, int op, const int* __restrict__ start_pos)
{
    extern __shared__ __half hsm[];
    int tid = threadIdx.x, lane = tid & 31, warp = tid >> 5;
    int wm = warp & 1, wn = warp >> 1;
    int m0 = blockIdx.x * 128, n0 = blockIdx.y * 128;

    int crow = tid >> 1;
    int cc16 = (tid & 1) * 4;
    const __half* aSrc = A  + (size_t)(m0 + crow) * K + cc16 * 8;
    const __half* bSrc = Wt + (size_t)(n0 + crow) * K + cc16 * 8;
    uint32_t asBase = (uint32_t)__cvta_generic_to_shared(hsm);
    uint32_t bsBase = asBase + 3 * TILE_H * 2;
    uint32_t cOff = (uint32_t)(crow * 144 + cc16 * 16);

    float acc[4][4][4];
    #pragma unroll
    for (int i = 0; i < 4; i++)
        #pragma unroll
        for (int j = 0; j < 4; j++)
            #pragma unroll
            for (int r = 0; r < 4; r++) acc[i][j][r] = 0.f;

    int KT = K >> 6;

    #pragma unroll
    for (int s = 0; s < 2; s++) {
        int kk = s * 64;
        #pragma unroll
        for (int i = 0; i < 4; i++)
            cpasync16(asBase + s * (TILE_H * 2) + cOff + i * 16, aSrc + kk + i * 8);
        #pragma unroll
        for (int i = 0; i < 4; i++)
            cpasync16(bsBase + s * (TILE_H * 2) + cOff + i * 16, bSrc + kk + i * 8);
        asm volatile("cp.async.commit_group;");
    }

    uint32_t aLd = (uint32_t)((wm * 64 + (lane & 15)) * 144 + (lane >> 4) * 16);
    uint32_t bLd = (uint32_t)((wn * 32 + (lane & 15)) * 144 + (lane >> 4) * 16);

    for (int kt = 0; kt < KT; ++kt) {
        asm volatile("cp.async.wait_group 1;" ::: "memory");
        __syncthreads();

        if (kt + 2 < KT) {
            int s = (kt + 2) % 3;
            int kk = (kt + 2) * 64;
            #pragma unroll
            for (int i = 0; i < 4; i++)
                cpasync16(asBase + s * (TILE_H * 2) + cOff + i * 16, aSrc + kk + i * 8);
            #pragma unroll
            for (int i = 0; i < 4; i++)
                cpasync16(bsBase + s * (TILE_H * 2) + cOff + i * 16, bSrc + kk + i * 8);
        }
        asm volatile("cp.async.commit_group;");

        uint32_t aSB = asBase + (kt % 3) * (TILE_H * 2);
        uint32_t bSB = bsBase + (kt % 3) * (TILE_H * 2);

        #pragma unroll
        for (int ks = 0; ks < 4; ++ks) {
            uint32_t afr[4][4], br[2][4];
            #pragma unroll
            for (int im = 0; im < 4; im++)
                ldsm4(aSB + aLd + im * 2304 + ks * 32,
                      afr[im][0], afr[im][1], afr[im][2], afr[im][3]);
            #pragma unroll
            for (int p = 0; p < 2; p++)
                ldsm4(bSB + bLd + p * 2304 + ks * 32,
                      br[p][0], br[p][1], br[p][2], br[p][3]);
            #pragma unroll
            for (int im = 0; im < 4; im++)
                #pragma unroll
                for (int in = 0; in < 4; in++) {
                    uint32_t bb[2] = { br[in >> 1][in & 1], br[in >> 1][(in & 1) + 2] };
                    mmah(acc[im][in], afr[im], bb);
                }
        }
    }

    int rbase = m0 + wm * 64 + (lane >> 2);
    int cbase = n0 + wn * 32 + ((lane & 3) << 1);
    #pragma unroll
    for (int im = 0; im < 4; im++) {
        #pragma unroll
        for (int hh = 0; hh < 2; hh++) {
            int row = rbase + im * 16 + hh * 8;
            bool zero = false;
            if (op == 2) zero = (row & 1023) < start_pos[row >> 10];
            #pragma unroll
            for (int in = 0; in < 4; in++) {
                int col = cbase + in * 8;
                float v0 = acc[im][in][hh * 2 + 0] + bias[col];
                float v1 = acc[im][in][hh * 2 + 1] + bias[col + 1];
                if (op == 1) {
                    v0 = 0.5f * v0 * (1.0f + erff(v0 * 0.70710678118654752f));
                    v1 = 0.5f * v1 * (1.0f + erff(v1 * 0.70710678118654752f));
                }
                if (op == 0 || op == 1) {
                    *(__half2*)((__half*)Cv + (size_t)row * N + col) =
                        __floats2half2_rn(v0, v1);
                } else {
                    if (zero) { v0 = 0.f; v1 = 0.f; }
                    float2 o; o.x = v0; o.y = v1;
                    *(float2*)((float*)Cv + (size_t)row * N + col) = o;
                }
            }
        }
    }
}

// ---------------------- fp16 flash attention (ldmatrix) --------------------
#define AH 72

__global__ __launch_bounds__(128)
void attn_h_kernel(const __half* __restrict__ QKV, __half* __restrict__ O,
                   const int* __restrict__ start_pos)
{
    __shared__ __half sQ[64 * AH], sK[64 * AH], sVt[64 * AH], sP[64 * AH];
    uint32_t* pW = (uint32_t*)sP;

    int tid = threadIdx.x, lane = tid & 31, warp = tid >> 5;
    int qt = blockIdx.x, bh = blockIdx.y;
    int b = bh >> 4, h = bh & 15;
    int sp = start_pos[b];
    float slope = exp2f(-0.5f * (float)(h + 1));
    int brow = b * Sz;

    const __half* Qg = QKV + h * 64;
    const __half* Kg = QKV + 1024 + h * 64;
    const __half* Vg = QKV + 2048 + h * 64;

    uint32_t sQb = (uint32_t)__cvta_generic_to_shared(sQ);
    uint32_t sKb = (uint32_t)__cvta_generic_to_shared(sK);
    uint32_t sVb = (uint32_t)__cvta_generic_to_shared(sVt);
    uint32_t sPb = (uint32_t)__cvta_generic_to_shared(sP);

    const __half2 hscale = __float2half2_rn(0.125f);
    for (int i = tid; i < 64 * 16; i += 128) {
        int row = i >> 4, d4 = (i & 15) * 4;
        uint2 u = *(const uint2*)(Qg + (size_t)(brow + qt * 64 + row) * QKVN + d4);
        __half2 h0 = __hmul2(*(__half2*)&u.x, hscale);
        __half2 h1 = __hmul2(*(__half2*)&u.y, hscale);
        uint2 o; o.x = *(uint32_t*)&h0; o.y = *(uint32_t*)&h1;
        *(uint2*)(sQ + row * AH + d4) = o;
    }

    int qrow = warp * 16 + (lane >> 2);
    int cA   = lane & 3;
    int ig0 = qt * 64 + qrow, ig1 = ig0 + 8;

    // ldmatrix lane offsets
    uint32_t fragQ = (uint32_t)((warp * 16 + (lane & 15)) * 144 + (lane >> 4) * 16);
    uint32_t fragB = (uint32_t)((lane & 15) * 144 + (lane >> 4) * 16);

    float m0 = -1e30f, m1 = -1e30f, l0 = 0.f, l1 = 0.f;
    float oacc[8][4];
    #pragma unroll
    for (int n = 0; n < 8; n++)
        #pragma unroll
        for (int r = 0; r < 4; r++) oacc[n][r] = 0.f;

    int ktmax = (qt * 64 >= sp) ? qt : 15;

    for (int kt = 0; kt <= ktmax; ++kt) {
        __syncthreads();
        for (int i = tid; i < 64 * 16; i += 128) {
            int row = i >> 4, d4 = (i & 15) * 4;
            uint2 uk = *(const uint2*)(Kg + (size_t)(brow + kt * 64 + row) * QKVN + d4);
            *(uint2*)(sK + row * AH + d4) = uk;
            uint2 uv = *(const uint2*)(Vg + (size_t)(brow + kt * 64 + row) * QKVN + d4);
            __half vh[4];
            *(uint2*)vh = uv;
            #pragma unroll
            for (int j = 0; j < 4; j++)
                sVt[(d4 + j) * AH + row] = vh[j];
        }
        __syncthreads();

        // ---- scores = Q @ K^T ----
        float sacc[8][4];
        #pragma unroll
        for (int n = 0; n < 8; n++)
            #pragma unroll
            for (int r = 0; r < 4; r++) sacc[n][r] = 0.f;

        #pragma unroll
        for (int ks = 0; ks < 4; ++ks) {
            uint32_t af[4], br[4][4];
            ldsm4(sQb + fragQ + ks * 32, af[0], af[1], af[2], af[3]);
            #pragma unroll
            for (int p = 0; p < 4; p++)
                ldsm4(sKb + fragB + p * 2304 + ks * 32,
                      br[p][0], br[p][1], br[p][2], br[p][3]);
            #pragma unroll
            for (int n = 0; n < 8; n++) {
                uint32_t bb[2] = { br[n >> 1][n & 1], br[n >> 1][(n & 1) + 2] };
                mmah(sacc[n], af, bb);
            }
        }

        // ---- alibi + mask ----
        #pragma unroll
        for (int n = 0; n < 8; n++) {
            int jg = kt * 64 + n * 8 + cA * 2;
            #pragma unroll
            for (int half = 0; half < 2; half++) {
                int j = jg + half;
                float al = slope * (float)(j - sp);
                bool ok0 = (j <= ig0) || (ig0 < sp) || (j < sp);
                bool ok1 = (j <= ig1) || (ig1 < sp) || (j < sp);
                sacc[n][half]     = ok0 ? sacc[n][half]     + al : -1e30f;
                sacc[n][half + 2] = ok1 ? sacc[n][half + 2] + al : -1e30f;
            }
        }

        // ---- row max ----
        float t0 = -1e30f, t1 = -1e30f;
        #pragma unroll
        for (int n = 0; n < 8; n++) {
            t0 = fmaxf(t0, fmaxf(sacc[n][0], sacc[n][1]));
            t1 = fmaxf(t1, fmaxf(sacc[n][2], sacc[n][3]));
        }
        t0 = fmaxf(t0, __shfl_xor_sync(0xffffffffu, t0, 1));
        t0 = fmaxf(t0, __shfl_xor_sync(0xffffffffu, t0, 2));
        t1 = fmaxf(t1, __shfl_xor_sync(0xffffffffu, t1, 1));
        t1 = fmaxf(t1, __shfl_xor_sync(0xffffffffu, t1, 2));

        float mn0 = fmaxf(m0, t0), mn1 = fmaxf(m1, t1);
        float scl0 = __expf(m0 - mn0), scl1 = __expf(m1 - mn1);
        m0 = mn0; m1 = mn1;

        float ls0 = 0.f, ls1 = 0.f;
        #pragma unroll
        for (int n = 0; n < 8; n++) {
            __half2 hp0 = __floats2half2_rn(__expf(sacc[n][0] - mn0),
                                            __expf(sacc[n][1] - mn0));
            __half2 hp1 = __floats2half2_rn(__expf(sacc[n][2] - mn1),
                                            __expf(sacc[n][3] - mn1));
            float2 f0 = __half22float2(hp0);
            float2 f1 = __half22float2(hp1);
            ls0 += f0.x + f0.y;
            ls1 += f1.x + f1.y;
            pW[(qrow)     * 36 + n * 4 + cA] = *(uint32_t*)&hp0;
            pW[(qrow + 8) * 36 + n * 4 + cA] = *(uint32_t*)&hp1;
        }
        ls0 += __shfl_xor_sync(0xffffffffu, ls0, 1);
        ls0 += __shfl_xor_sync(0xffffffffu, ls0, 2);
        ls1 += __shfl_xor_sync(0xffffffffu, ls1, 1);
        ls1 += __shfl_xor_sync(0xffffffffu, ls1, 2);
        l0 = l0 * scl0 + ls0;
        l1 = l1 * scl1 + ls1;

        #pragma unroll
        for (int n = 0; n < 8; n++) {
            oacc[n][0] *= scl0; oacc[n][1] *= scl0;
            oacc[n][2] *= scl1; oacc[n][3] *= scl1;
        }
        __syncwarp();

        // ---- O += P @ V  (A = P rows, B = Vt[d][k]) ----
        #pragma unroll
        for (int ks = 0; ks < 4; ++ks) {
            uint32_t af[4], br[4][4];
            ldsm4(sPb + fragQ + ks * 32, af[0], af[1], af[2], af[3]);
            #pragma unroll
            for (int p = 0; p < 4; p++)
                ldsm4(sVb + fragB + p * 2304 + ks * 32,
                      br[p][0], br[p][1], br[p][2], br[p][3]);
            #pragma unroll
            for (int n = 0; n < 8; n++) {
                uint32_t bb[2] = { br[n >> 1][n & 1], br[n >> 1][(n & 1) + 2] };
                mmah(oacc[n], af, bb);
            }
        }
        __syncwarp();
    }

    float inv0 = 1.f / l0, inv1 = 1.f / l1;
    size_t orow0 = (size_t)(brow + qt * 64 + qrow) * Hz + h * 64;
    size_t orow1 = orow0 + (size_t)8 * Hz;
    #pragma unroll
    for (int n = 0; n < 8; n++) {
        int col = n * 8 + cA * 2;
        *(__half2*)(O + orow0 + col) = __floats2half2_rn(oacc[n][0] * inv0, oacc[n][1] * inv0);
        *(__half2*)(O + orow1 + col) = __floats2half2_rn(oacc[n][2] * inv1, oacc[n][3] * inv1);
    }
}

// ------------------------ fused residual + layernorm -----------------------
__inline__ __device__ float warp_sum(float v) {
    #pragma unroll
    for (int o = 16; o; o >>= 1) v += __shfl_xor_sync(0xffffffffu, v, o);
    return v;
}

__global__ void add_ln_kernel(float* __restrict__ x, __half* __restrict__ xch,
                              const float* __restrict__ t,
                              const float* __restrict__ g, const float* __restrict__ b)
{
    int row = blockIdx.x;
    int tid = threadIdx.x;
    size_t off = (size_t)row * Hz + tid * 4;

    float4 xv = *(const float4*)(x + off);
    float4 tv = *(const float4*)(t + off);
    float v0 = xv.x + tv.x, v1 = xv.y + tv.y, v2 = xv.z + tv.z, v3 = xv.w + tv.w;

    float s  = v0 + v1 + v2 + v3;
    float s2 = v0 * v0 + v1 * v1 + v2 * v2 + v3 * v3;

    __shared__ float sh1[8], sh2[8];
    int lane = tid & 31, wid = tid >> 5;
    s  = warp_sum(s);
    s2 = warp_sum(s2);
    if (lane == 0) { sh1[wid] = s; sh2[wid] = s2; }
    __syncthreads();
    if (wid == 0) {
        float a = (lane < 8) ? sh1[lane] : 0.f;
        float c = (lane < 8) ? sh2[lane] : 0.f;
        a = warp_sum(a);
        c = warp_sum(c);
        if (lane == 0) { sh1[0] = a; sh2[0] = c; }
    }
    __syncthreads();

    float mu  = sh1[0] * (1.0f / Hz);
    float var = sh2[0] * (1.0f / Hz) - mu * mu;
    float inv = rsqrtf(var + 1e-5f);

    int cbase = tid * 4;
    float4 gv = *(const float4*)(g + cbase);
    float4 bv = *(const float4*)(b + cbase);
    float4 out;
    out.x = (v0 - mu) * inv * gv.x + bv.x;
    out.y = (v1 - mu) * inv * gv.y + bv.y;
    out.z = (v2 - mu) * inv * gv.z + bv.z;
    out.w = (v3 - mu) * inv * gv.w + bv.w;
    *(float4*)(x + off) = out;
    *(__half2*)(xch + off)     = __floats2half2_rn(out.x, out.y);
    *(__half2*)(xch + off + 2) = __floats2half2_rn(out.z, out.w);
}

// --------------------------------- launch ----------------------------------
extern "C" void kernel_launch(void* const* d_in, const int* in_sizes, int n_in,
                              void* d_out, int out_size)
{
    const int*   ids  = (const int*)d_in[0];
    const int*   sp   = (const int*)d_in[1];
    const float* emb  = (const float*)d_in[2];
    const float* Wq   = (const float*)d_in[3];
    const float* bq   = (const float*)d_in[4];
    const float* Wk   = (const float*)d_in[5];
    const float* bk   = (const float*)d_in[6];
    const float* Wv   = (const float*)d_in[7];
    const float* bv   = (const float*)d_in[8];
    const float* Wo   = (const float*)d_in[9];
    const float* bo   = (const float*)d_in[10];
    const float* ln1g = (const float*)d_in[11];
    const float* ln1b = (const float*)d_in[12];
    const float* ln2g = (const float*)d_in[13];
    const float* ln2b = (const float*)d_in[14];
    const float* W1   = (const float*)d_in[15];
    const float* b1   = (const float*)d_in[16];
    const float* W2   = (const float*)d_in[17];
    const float* b2   = (const float*)d_in[18];
    const float* Wf   = (const float*)d_in[19];
    const float* bf   = (const float*)d_in[20];
    float* out = (float*)d_out;

    float *x, *tmp, *bqkv;
    __half *xch, *qkv, *attnc, *ffc, *w;
    cudaGetSymbolAddress((void**)&x,     g_x);
    cudaGetSymbolAddress((void**)&xch,   g_xch);
    cudaGetSymbolAddress((void**)&qkv,   g_qkv);
    cudaGetSymbolAddress((void**)&attnc, g_attnc);
    cudaGetSymbolAddress((void**)&tmp,   g_tmp);
    cudaGetSymbolAddress((void**)&ffc,   g_ffc);
    cudaGetSymbolAddress((void**)&w,     g_w);
    cudaGetSymbolAddress((void**)&bqkv,  g_bqkv);

    cudaFuncSetAttribute(gemm_h_kernel, cudaFuncAttributeMaxDynamicSharedMemorySize, GEMM_SMEM);

    dim3 tb(32, 8);
    // batched weight prep: Wq/Wk/Wv -> interleaved qkvT slices, Wo, W1, W2, Wf
    transT_b_kernel<<<dim3(Hz / 32, Hz / 32, Lz), tb>>>(
        Wq, w + OFF_QKV,                     Hz, Hz, (size_t)Hz * Hz, (size_t)Hz * QKVN);
    transT_b_kernel<<<dim3(Hz / 32, Hz / 32, Lz), tb>>>(
        Wk, w + OFF_QKV + (size_t)1024 * Hz, Hz, Hz, (size_t)Hz * Hz, (size_t)Hz * QKVN);
    transT_b_kernel<<<dim3(Hz / 32, Hz / 32, Lz), tb>>>(
        Wv, w + OFF_QKV + (size_t)2048 * Hz, Hz, Hz, (size_t)Hz * Hz, (size_t)Hz * QKVN);
    transT_b_kernel<<<dim3(Hz / 32, Hz / 32, Lz), tb>>>(
        Wo, w + OFF_WO, Hz, Hz, (size_t)Hz * Hz, (size_t)Hz * Hz);
    transT_b_kernel<<<dim3(Hz / 32, DFz / 32, Lz), tb>>>(
        W1, w + OFF_W1, Hz, DFz, (size_t)Hz * DFz, (size_t)Hz * DFz);
    transT_b_kernel<<<dim3(DFz / 32, Hz / 32, Lz), tb>>>(
        W2, w + OFF_W2, DFz, Hz, (size_t)DFz * Hz, (size_t)DFz * Hz);
    transT_b_kernel<<<dim3(Hz / 32, Vz / 32, 1), tb>>>(
        Wf, w + OFF_WF, Hz, Vz, 0, 0);
    cvt_bias_kernel<<<(Lz * QKVN) / 256, 256>>>(bq, bk, bv, bqkv);

    embed_kernel<<<Mz, 256>>>(ids, emb, x, xch);

    for (int l = 0; l < Lz; ++l) {
        gemm_h_kernel<<<dim3(Mz / 128, QKVN / 128), 256, GEMM_SMEM>>>(
            xch, w + OFF_QKV + (size_t)l * Hz * QKVN, bqkv + l * QKVN, qkv,
            Mz, QKVN, Hz, 0, sp);

        attn_h_kernel<<<dim3(Sz / 64, Bz * NHz), 128>>>(qkv, attnc, sp);

        gemm_h_kernel<<<dim3(Mz / 128, Hz / 128), 256, GEMM_SMEM>>>(
            attnc, w + OFF_WO + (size_t)l * Hz * Hz, bo + l * Hz, tmp,
            Mz, Hz, Hz, 3, sp);
        add_ln_kernel<<<Mz, 256>>>(x, xch, tmp, ln1g + l * Hz, ln1b + l * Hz);

        gemm_h_kernel<<<dim3(Mz / 128, DFz / 128), 256, GEMM_SMEM>>>(
            xch, w + OFF_W1 + (size_t)l * Hz * DFz, b1 + l * DFz, ffc,
            Mz, DFz, Hz, 1, sp);
        gemm_h_kernel<<<dim3(Mz / 128, Hz / 128), 256, GEMM_SMEM>>>(
            ffc, w + OFF_W2 + (size_t)l * DFz * Hz, b2 + l * Hz, tmp,
            Mz, Hz, DFz, 3, sp);
        add_ln_kernel<<<Mz, 256>>>(x, xch, tmp, ln2g + l * Hz, ln2b + l * Hz);
    }

    gemm_h_kernel<<<dim3(Mz / 128, Vz / 128), 256, GEMM_SMEM>>>(
        xch, w + OFF_WF, bf, out, Mz, Vz, Hz, 2, sp);
}